// round 9
// baseline (speedup 1.0000x reference)
#include <cuda_runtime.h>
#include <cuda_bf16.h>
#include <math.h>

#define NN 50000
#define RR 6
#define EE 32768
#define HH 256
#define FF 16
#define NHH 8
#define KVIN (HH + FF)      // 272

typedef __nv_bfloat16 bf16;

// ---------------- fp32 scratch (single relation; reused across loop) ------
__device__ float g_kvb[EE * 512];        // [e][ kb(256) | vb(256) ]
__device__ float g_qb[EE * HH];
__device__ float g_scores[EE * NHH];
__device__ float g_denom[NN * NHH];
__device__ unsigned g_key[NN * NHH];
__device__ float g_agg[NN * HH];
__device__ float g_relout[(size_t)NN * RR * HH];    // [N, R*H]
__device__ float g_h[NN * HH];
__device__ float g_stacked[NN * 3 * HH];
__device__ float g_t[NN * 3 * (HH / 2)];
__device__ float g_interagg[NN * HH];
__device__ float g_comb[NN * HH];

// ---------------- bf16 hi/lo planes (activations) ----------------
__device__ bf16 g_kvin_h[EE * KVIN],  g_kvin_l[EE * KVIN];
__device__ bf16 g_xdst_h[EE * HH],    g_xdst_l[EE * HH];
__device__ bf16 g_agg_h[NN * HH],     g_agg_l[NN * HH];
__device__ bf16 g_relout_h[(size_t)NN * RR * HH],  g_relout_l[(size_t)NN * RR * HH];
__device__ bf16 g_paths_h[NN * 3 * HH],   g_paths_l[NN * 3 * HH];
__device__ bf16 g_stacked_h[NN * 3 * HH], g_stacked_l[NN * 3 * HH];
__device__ bf16 g_combin_h[NN * 2 * HH],  g_combin_l[NN * 2 * HH];

// ---------------- bf16 hi/lo planes (weights) ----------------
__device__ bf16 g_Wq_h[RR * HH * HH],    g_Wq_l[RR * HH * HH];
__device__ bf16 g_Wkv_h[RR * KVIN * 512], g_Wkv_l[RR * KVIN * 512];
__device__ float g_bkv[RR * 512];
__device__ bf16 g_Wm_h[RR * HH * HH],    g_Wm_l[RR * HH * HH];
__device__ bf16 g_Wir1_h[RR * HH * HH],  g_Wir1_l[RR * HH * HH];
__device__ bf16 g_Wmp_h[3 * HH * HH],    g_Wmp_l[3 * HH * HH];
__device__ bf16 g_Wa1_h[HH * HH / 2],    g_Wa1_l[HH * HH / 2];
__device__ bf16 g_Wc_h[2 * HH * HH],     g_Wc_l[2 * HH * HH];

__device__ __forceinline__ float gelu_exact(float x) {
    return 0.5f * x * (1.0f + erff(x * 0.70710678118654752f));
}
__device__ __forceinline__ void split2(float v, bf16& hi, bf16& lo) {
    hi = __float2bfloat16(v);
    lo = __float2bfloat16(v - __bfloat162float(hi));
}
__device__ __forceinline__ unsigned enc_f(float f) {
    unsigned b = __float_as_uint(f);
    return (b & 0x80000000u) ? ~b : (b | 0x80000000u);
}
__device__ __forceinline__ float dec_f(unsigned u) {
    return (u & 0x80000000u) ? __uint_as_float(u ^ 0x80000000u)
                             : __uint_as_float(~u);
}
// 128-bit no-return reduction (REDG.128), sm_90+
__device__ __forceinline__ void red4(float* addr, float4 v) {
    asm volatile("red.global.add.v4.f32 [%0], {%1,%2,%3,%4};"
                 :: "l"(addr), "f"(v.x), "f"(v.y), "f"(v.z), "f"(v.w)
                 : "memory");
}

// ================= tensor-core GEMM (bf16 split, cp.async 4-stage) ========
#define RS_A 24
#define RS_B 136
#define STAGE_BYTES 20992   // Ahi 6144 | Alo 6144 | Bhi 4352 | Blo 4352
#define GEMM_SMEM (4 * STAGE_BYTES)

__device__ __forceinline__ void cp16(unsigned d, const void* s, unsigned sz) {
    asm volatile("cp.async.cg.shared.global [%0], [%1], 16, %2;"
                 :: "r"(d), "l"(s), "r"(sz));
}
__device__ __forceinline__ void ldsm_x4(unsigned& r0, unsigned& r1,
                                        unsigned& r2, unsigned& r3,
                                        unsigned addr) {
    asm volatile("ldmatrix.sync.aligned.m8n8.x4.shared.b16 {%0,%1,%2,%3}, [%4];"
                 : "=r"(r0), "=r"(r1), "=r"(r2), "=r"(r3) : "r"(addr));
}
__device__ __forceinline__ void ldsm_x4t(unsigned& r0, unsigned& r1,
                                         unsigned& r2, unsigned& r3,
                                         unsigned addr) {
    asm volatile("ldmatrix.sync.aligned.m8n8.x4.trans.shared.b16 {%0,%1,%2,%3}, [%4];"
                 : "=r"(r0), "=r"(r1), "=r"(r2), "=r"(r3) : "r"(addr));
}
__device__ __forceinline__ void mma16816(float* c, const unsigned* a,
                                         unsigned b0, unsigned b1) {
    asm volatile(
        "mma.sync.aligned.m16n8k16.row.col.f32.bf16.bf16.f32 "
        "{%0,%1,%2,%3},{%4,%5,%6,%7},{%8,%9},{%0,%1,%2,%3};"
        : "+f"(c[0]), "+f"(c[1]), "+f"(c[2]), "+f"(c[3])
        : "r"(a[0]), "r"(a[1]), "r"(a[2]), "r"(a[3]), "r"(b0), "r"(b1));
}

// NOTE: no min-blocks clause — 128-reg cap forces spills (R4 regression).
__global__ __launch_bounds__(256)
void mma_gemm_batched(const bf16* __restrict__ Ahi, const bf16* __restrict__ Alo,
                      int lda, long long sA,
                      const bf16* __restrict__ Bhi, const bf16* __restrict__ Blo,
                      int ldb, long long sB,
                      const float* __restrict__ bias, int sBias,
                      float* __restrict__ C, int ldc, long long sC,
                      bf16* __restrict__ Chi, bf16* __restrict__ Clo,
                      int ldc2, long long sC2,
                      int M, int Nc, int K, int act)
{
    extern __shared__ __align__(128) char smem[];
    const unsigned smemBase = (unsigned)__cvta_generic_to_shared(smem);

    const int z = blockIdx.z;
    Ahi += (size_t)z * sA;  Alo += (size_t)z * sA;
    Bhi += (size_t)z * sB;  Blo += (size_t)z * sB;
    bias += (size_t)z * sBias;
    C += (size_t)z * sC;
    if (Chi) { Chi += (size_t)z * sC2; Clo += (size_t)z * sC2; }

    const int tid = threadIdx.x;
    const int lane = tid & 31;
    const int w = tid >> 5;
    const int wm = w & 3;
    const int wn = w >> 2;
    const int rowBase = blockIdx.y * 128;
    const int colBase = blockIdx.x * 128;
    const int nChunks = K >> 4;

    float acc[2][8][4];
#pragma unroll
    for (int i = 0; i < 2; i++)
#pragma unroll
        for (int j = 0; j < 8; j++)
#pragma unroll
            for (int q = 0; q < 4; q++) acc[i][j][q] = 0.0f;

    unsigned offA[2], offB[4];
#pragma unroll
    for (int mt = 0; mt < 2; mt++)
        offA[mt] = (wm * 32 + mt * 16 + (lane & 15)) * RS_A + (lane >> 4) * 8;
#pragma unroll
    for (int g = 0; g < 4; g++)
        offB[g] = (lane & 15) * RS_B + wn * 64 + g * 16 + (lane >> 4) * 8;

    const int aRow = tid >> 1;
    const int aCh  = (tid & 1) << 3;
    const int bRow = tid >> 4;
    const int bCh  = (tid & 15) << 3;
    const int aSafe = (rowBase + aRow < M) ? (rowBase + aRow) : 0;
    const unsigned aSz = (rowBase + aRow < M) ? 16u : 0u;

    auto issue_stage = [&](int c) {
        if (c < nChunks) {
            const int k0 = c << 4;
            const unsigned sb = smemBase + (c & 3) * STAGE_BYTES;
            size_t ao = (size_t)aSafe * lda + k0 + aCh;
            unsigned da = sb + (aRow * RS_A + aCh) * 2;
            cp16(da,        Ahi + ao, aSz);
            cp16(da + 6144, Alo + ao, aSz);
            size_t bo = (size_t)(k0 + bRow) * ldb + colBase + bCh;
            unsigned db = sb + 12288 + (bRow * RS_B + bCh) * 2;
            cp16(db,        Bhi + bo, 16u);
            cp16(db + 4352, Blo + bo, 16u);
        }
        asm volatile("cp.async.commit_group;" ::);
    };

    issue_stage(0); issue_stage(1); issue_stage(2);

    for (int k = 0; k < nChunks; k++) {
        asm volatile("cp.async.wait_group 2;" ::);
        __syncthreads();
        issue_stage(k + 3);

        const unsigned sb = smemBase + (k & 3) * STAGE_BYTES;
        unsigned ah[2][4], al[2][4];
#pragma unroll
        for (int mt = 0; mt < 2; mt++) {
            ldsm_x4(ah[mt][0], ah[mt][1], ah[mt][2], ah[mt][3], sb + offA[mt] * 2);
            ldsm_x4(al[mt][0], al[mt][1], al[mt][2], al[mt][3], sb + 6144 + offA[mt] * 2);
        }
#pragma unroll
        for (int g = 0; g < 4; g++) {
            unsigned bh[4], bl[4];
            ldsm_x4t(bh[0], bh[1], bh[2], bh[3], sb + 12288 + offB[g] * 2);
            ldsm_x4t(bl[0], bl[1], bl[2], bl[3], sb + 16640 + offB[g] * 2);
#pragma unroll
            for (int mt = 0; mt < 2; mt++) {
                float* a0 = acc[mt][g * 2];
                float* a1 = acc[mt][g * 2 + 1];
                mma16816(a0, ah[mt], bh[0], bh[1]);
                mma16816(a0, ah[mt], bl[0], bl[1]);
                mma16816(a0, al[mt], bh[0], bh[1]);
                mma16816(a1, ah[mt], bh[2], bh[3]);
                mma16816(a1, ah[mt], bl[2], bl[3]);
                mma16816(a1, al[mt], bh[2], bh[3]);
            }
        }
    }

#pragma unroll
    for (int mt = 0; mt < 2; mt++) {
        int r0 = rowBase + wm * 32 + mt * 16 + (lane >> 2);
#pragma unroll
        for (int half = 0; half < 2; half++) {
            int r = r0 + half * 8;
            if (r >= M) continue;
#pragma unroll
            for (int nt = 0; nt < 8; nt++) {
                int cg = colBase + wn * 64 + nt * 8 + (lane & 3) * 2;
                float v0 = acc[mt][nt][half * 2]     + bias[cg];
                float v1 = acc[mt][nt][half * 2 + 1] + bias[cg + 1];
                if (act == 1) { v0 = gelu_exact(v0); v1 = gelu_exact(v1); }
                else if (act == 2) { v0 = tanhf(v0); v1 = tanhf(v1); }
                *(float2*)&C[(size_t)r * ldc + cg] = make_float2(v0, v1);
                if (Chi) {
                    bf16 h0, l0, h1, l1;
                    split2(v0, h0, l0); split2(v1, h1, l1);
                    __nv_bfloat162 ph; ph.x = h0; ph.y = h1;
                    __nv_bfloat162 pl; pl.x = l0; pl.y = l1;
                    *(__nv_bfloat162*)&Chi[(size_t)r * ldc2 + cg] = ph;
                    *(__nv_bfloat162*)&Clo[(size_t)r * ldc2 + cg] = pl;
                }
            }
        }
    }
}

// ---------------- elementwise helpers ----------------
__global__ void split_kernel(const float* __restrict__ src,
                             bf16* __restrict__ hi, bf16* __restrict__ lo, int n)
{
    int i = blockIdx.x * 256 + threadIdx.x;
    if (i < n) split2(src[i], hi[i], lo[i]);
}

__global__ void pack_kv_kernel(const float* __restrict__ Wk,
                               const float* __restrict__ Wv)
{
    int i = blockIdx.x * 256 + threadIdx.x;   // over RR*KVIN*512
    if (i >= RR * KVIN * 512) return;
    int col = i & 511;
    int row = (i >> 9) % KVIN;
    int r = i / (512 * KVIN);
    float v = (col < HH) ? Wk[((size_t)r * KVIN + row) * HH + col]
                         : Wv[((size_t)r * KVIN + row) * HH + col - HH];
    split2(v, g_Wkv_h[i], g_Wkv_l[i]);
}

__global__ void pack_bkv_kernel(const float* __restrict__ bk,
                                const float* __restrict__ bv)
{
    int i = blockIdx.x * 256 + threadIdx.x;   // over RR*512
    if (i >= RR * 512) return;
    int col = i & 511;
    int r = i >> 9;
    g_bkv[i] = (col < HH) ? bk[r * HH + col] : bv[r * HH + col - HH];
}

// ---------------- per-relation kernels ----------------
__global__ void gather_kernel(const float* __restrict__ x,
                              const int* __restrict__ ei_r,
                              const float* __restrict__ ea_r)
{
    int e = blockIdx.x, t = threadIdx.x;
    int src = ei_r[e];
    int dst = ei_r[EE + e];
    split2(x[(size_t)src * HH + t], g_kvin_h[e * KVIN + t], g_kvin_l[e * KVIN + t]);
    split2(x[(size_t)dst * HH + t], g_xdst_h[e * HH + t],   g_xdst_l[e * HH + t]);
    if (t < FF)
        split2(ea_r[e * FF + t], g_kvin_h[e * KVIN + HH + t], g_kvin_l[e * KVIN + HH + t]);
}

__global__ void init_kernel()
{
    int idx = blockIdx.x * 256 + threadIdx.x;   // grid = NN blocks
    g_agg[idx] = 0.0f;
    if (idx < NN * NHH) { g_denom[idx] = 0.0f; g_key[idx] = 0u; }
}

__global__ void score_kernel(const int* __restrict__ dst_r,
                             const float* __restrict__ prior_r)
{
    int e = blockIdx.x, t = threadIdx.x;
    int h = t >> 5, lane = t & 31;
    float p = g_qb[e * HH + t] * g_kvb[e * 512 + t];
#pragma unroll
    for (int o = 16; o > 0; o >>= 1) p += __shfl_down_sync(0xFFFFFFFFu, p, o);
    if (lane == 0) {
        int dst = dst_r[e];
        float s = p * 0.17677669529663689f * prior_r[h];
        g_scores[e * NHH + h] = s;
        atomicMax(&g_key[dst * NHH + h], enc_f(s));
    }
}

__global__ void ex_kernel(const int* __restrict__ dst_r)
{
    int idx = blockIdx.x * 256 + threadIdx.x;   // EE*NHH
    int e = idx >> 3, h = idx & 7;
    int dst = dst_r[e];
    float m = dec_f(g_key[dst * NHH + h]);
    float ex = expf(g_scores[idx] - m);
    g_scores[idx] = ex;
    atomicAdd(&g_denom[dst * NHH + h], ex);
}

// 64 threads/block, 4 cols/thread, 128-bit REDG
__global__ void scatter_kernel(const int* __restrict__ dst_r)
{
    int e = blockIdx.x, t = threadIdx.x;
    int c = t << 2;
    int h = c >> 5;
    int dst = dst_r[e];
    float w = g_scores[e * NHH + h] / (g_denom[dst * NHH + h] + 1e-16f);
    float4 v = *(const float4*)&g_kvb[e * 512 + 256 + c];
    float4 p = make_float4(w * v.x, w * v.y, w * v.z, w * v.w);
    red4(&g_agg[(size_t)dst * HH + c], p);
}

// ---------------- inter-relation fusion ----------------
__global__ void inter_kernel(const float* __restrict__ Wir2,
                             const float* __restrict__ bir2)
{
    int n = blockIdx.x, t = threadIdx.x;
    int w = t >> 5, lane = t & 31;
    __shared__ float logit[RR];
    if (w < RR) {
        float s = 0.0f;
        for (int i = lane; i < HH; i += 32)
            s += g_h[(size_t)n * HH + i] * Wir2[i * RR + w];
#pragma unroll
        for (int o = 16; o > 0; o >>= 1) s += __shfl_down_sync(0xFFFFFFFFu, s, o);
        if (lane == 0) logit[w] = s + bir2[w];
    }
    __syncthreads();
    float l[RR]; float mx = -1e30f;
#pragma unroll
    for (int r = 0; r < RR; r++) { l[r] = logit[r]; mx = fmaxf(mx, l[r]); }
    float sum = 0.0f;
#pragma unroll
    for (int r = 0; r < RR; r++) { l[r] = expf(l[r] - mx); sum += l[r]; }
    float inv = 1.0f / sum;
    int c = t;
    const float* ro = g_relout + (size_t)n * (RR * HH);
    float acc = 0.0f;
#pragma unroll
    for (int r = 0; r < RR; r++) acc += l[r] * inv * ro[r * HH + c];
    g_interagg[(size_t)n * HH + c] = acc;
    size_t base = (size_t)n * 3 * HH;
    split2(ro[2 * HH + c] + ro[3 * HH + c], g_paths_h[base + c],          g_paths_l[base + c]);
    split2(ro[4 * HH + c] + ro[0 * HH + c], g_paths_h[base + HH + c],     g_paths_l[base + HH + c]);
    split2(ro[1 * HH + c] + ro[5 * HH + c], g_paths_h[base + 2 * HH + c], g_paths_l[base + 2 * HH + c]);
}

__global__ void meta_kernel(const float* __restrict__ Wa2,
                            const float* __restrict__ gm,
                            const float* __restrict__ bm_)
{
    int n = blockIdx.x, t = threadIdx.x;
    int w = t >> 5, lane = t & 31;
    __shared__ float sl[3];
    __shared__ float red[HH];
    __shared__ float s_mu, s_var;
    if (w < 3) {
        float s = 0.0f;
        for (int i = lane; i < HH / 2; i += 32)
            s += g_t[((size_t)n * 3 + w) * (HH / 2) + i] * Wa2[i];
#pragma unroll
        for (int o = 16; o > 0; o >>= 1) s += __shfl_down_sync(0xFFFFFFFFu, s, o);
        if (lane == 0) sl[w] = s;
    }
    __syncthreads();
    float a0 = sl[0], a1 = sl[1], a2 = sl[2];
    float mx = fmaxf(a0, fmaxf(a1, a2));
    float e0 = expf(a0 - mx), e1 = expf(a1 - mx), e2 = expf(a2 - mx);
    float inv = 1.0f / (e0 + e1 + e2);
    int c = t;
    const float* st = g_stacked + (size_t)n * 3 * HH;
    float mpre = (e0 * st[c] + e1 * st[HH + c] + e2 * st[2 * HH + c]) * inv;
    red[t] = mpre; __syncthreads();
    for (int s = 128; s > 0; s >>= 1) { if (t < s) red[t] += red[t + s]; __syncthreads(); }
    if (t == 0) s_mu = red[0] * (1.0f / HH);
    __syncthreads();
    float d = mpre - s_mu;
    red[t] = d * d; __syncthreads();
    for (int s = 128; s > 0; s >>= 1) { if (t < s) red[t] += red[t + s]; __syncthreads(); }
    if (t == 0) s_var = red[0] * (1.0f / HH);
    __syncthreads();
    float meta = d * rsqrtf(s_var + 1e-5f) * gm[c] + bm_[c];
    size_t base = (size_t)n * 2 * HH;
    split2(g_interagg[(size_t)n * HH + c], g_combin_h[base + c],      g_combin_l[base + c]);
    split2(meta,                           g_combin_h[base + HH + c], g_combin_l[base + HH + c]);
}

__global__ void final_kernel(const float* __restrict__ x,
                             const float* __restrict__ g,
                             const float* __restrict__ b,
                             float* __restrict__ out)
{
    int n = blockIdx.x, t = threadIdx.x;
    __shared__ float red[HH];
    __shared__ float s_mu, s_var;
    float v = x[(size_t)n * HH + t] + g_comb[(size_t)n * HH + t];
    red[t] = v; __syncthreads();
    for (int s = 128; s > 0; s >>= 1) { if (t < s) red[t] += red[t + s]; __syncthreads(); }
    if (t == 0) s_mu = red[0] * (1.0f / HH);
    __syncthreads();
    float d = v - s_mu;
    red[t] = d * d; __syncthreads();
    for (int s = 128; s > 0; s >>= 1) { if (t < s) red[t] += red[t + s]; __syncthreads(); }
    if (t == 0) s_var = red[0] * (1.0f / HH);
    __syncthreads();
    out[(size_t)n * HH + t] = d * rsqrtf(s_var + 1e-5f) * g[t] + b[t];
}

// ---------------- host ----------------
static inline void run_gemm(const bf16* Ah, const bf16* Al, int lda, long long sA,
                            const bf16* Bh, const bf16* Bl, int ldb, long long sB,
                            const float* bias, int sBias,
                            float* C, int ldc, long long sC,
                            bf16* Ch, bf16* Cl, int ldc2, long long sC2,
                            int M, int Nc, int K, int act, int Z)
{
    dim3 grid(Nc / 128, (M + 127) / 128, Z);
    mma_gemm_batched<<<grid, 256, GEMM_SMEM>>>(Ah, Al, lda, sA, Bh, Bl, ldb, sB,
                                               bias, sBias, C, ldc, sC,
                                               Ch, Cl, ldc2, sC2, M, Nc, K, act);
}
static inline void run_split(const float* src, bf16* hi, bf16* lo, size_t n)
{
    split_kernel<<<(unsigned)((n + 255) / 256), 256>>>(src, hi, lo, (int)n);
}

extern "C" void kernel_launch(void* const* d_in, const int* in_sizes, int n_in,
                              void* d_out, int out_size)
{
    const float* x    = (const float*)d_in[0];
    const int*   ei   = (const int*)d_in[1];
    const float* ea   = (const float*)d_in[2];
    const float* Wq   = (const float*)d_in[3];
    const float* bq   = (const float*)d_in[4];
    const float* Wk   = (const float*)d_in[5];
    const float* bk   = (const float*)d_in[6];
    const float* Wv   = (const float*)d_in[7];
    const float* bv   = (const float*)d_in[8];
    const float* prior= (const float*)d_in[9];
    const float* Wm   = (const float*)d_in[10];
    const float* bm   = (const float*)d_in[11];
    const float* Wir1 = (const float*)d_in[12];
    const float* bir1 = (const float*)d_in[13];
    const float* Wir2 = (const float*)d_in[14];
    const float* bir2 = (const float*)d_in[15];
    const float* Wmp  = (const float*)d_in[16];
    const float* bmp  = (const float*)d_in[17];
    const float* Wa1  = (const float*)d_in[18];
    const float* ba1  = (const float*)d_in[19];
    const float* Wa2  = (const float*)d_in[20];
    const float* gme  = (const float*)d_in[21];
    const float* bme  = (const float*)d_in[22];
    const float* Wc   = (const float*)d_in[23];
    const float* bc   = (const float*)d_in[24];
    const float* gout = (const float*)d_in[25];
    const float* bout = (const float*)d_in[26];
    float* out = (float*)d_out;

    cudaFuncSetAttribute(mma_gemm_batched,
                         cudaFuncAttributeMaxDynamicSharedMemorySize, GEMM_SMEM);

#define SYM(p, s) { void* tmp; cudaGetSymbolAddress(&tmp, s); p = (decltype(p))tmp; }
    float *p_kvb, *p_qb, *p_agg, *p_relout, *p_h, *p_stacked, *p_t, *p_comb, *p_bkv;
    SYM(p_kvb, g_kvb); SYM(p_qb, g_qb); SYM(p_agg, g_agg);
    SYM(p_relout, g_relout); SYM(p_h, g_h); SYM(p_stacked, g_stacked);
    SYM(p_t, g_t); SYM(p_comb, g_comb); SYM(p_bkv, g_bkv);
    bf16 *kvin_h, *kvin_l, *xdst_h, *xdst_l, *agg_h, *agg_l,
         *relout_h, *relout_l, *paths_h, *paths_l, *stacked_h, *stacked_l,
         *combin_h, *combin_l;
    SYM(kvin_h, g_kvin_h); SYM(kvin_l, g_kvin_l);
    SYM(xdst_h, g_xdst_h); SYM(xdst_l, g_xdst_l);
    SYM(agg_h, g_agg_h);   SYM(agg_l, g_agg_l);
    SYM(relout_h, g_relout_h); SYM(relout_l, g_relout_l);
    SYM(paths_h, g_paths_h);   SYM(paths_l, g_paths_l);
    SYM(stacked_h, g_stacked_h); SYM(stacked_l, g_stacked_l);
    SYM(combin_h, g_combin_h);   SYM(combin_l, g_combin_l);
    bf16 *Wq_h, *Wq_l, *Wkv_h, *Wkv_l, *Wm_h, *Wm_l,
         *Wir1_h, *Wir1_l, *Wmp_h, *Wmp_l, *Wa1_h, *Wa1_l, *Wc_h, *Wc_l;
    SYM(Wq_h, g_Wq_h); SYM(Wq_l, g_Wq_l);
    SYM(Wkv_h, g_Wkv_h); SYM(Wkv_l, g_Wkv_l);
    SYM(Wm_h, g_Wm_h); SYM(Wm_l, g_Wm_l);
    SYM(Wir1_h, g_Wir1_h); SYM(Wir1_l, g_Wir1_l);
    SYM(Wmp_h, g_Wmp_h);   SYM(Wmp_l, g_Wmp_l);
    SYM(Wa1_h, g_Wa1_h);   SYM(Wa1_l, g_Wa1_l);
    SYM(Wc_h, g_Wc_h);     SYM(Wc_l, g_Wc_l);
#undef SYM

    // weight prep (batched, tiny)
    run_split(Wq,   Wq_h,   Wq_l,   RR * HH * HH);
    pack_kv_kernel<<<(RR * KVIN * 512 + 255) / 256, 256>>>(Wk, Wv);
    pack_bkv_kernel<<<(RR * 512 + 255) / 256, 256>>>(bk, bv);
    run_split(Wm,   Wm_h,   Wm_l,   RR * HH * HH);
    run_split(Wir1, Wir1_h, Wir1_l, RR * HH * HH);
    run_split(Wmp,  Wmp_h,  Wmp_l,  3 * HH * HH);
    run_split(Wa1,  Wa1_h,  Wa1_l,  HH * HH / 2);
    run_split(Wc,   Wc_h,   Wc_l,   2 * HH * HH);

    // per-relation pipeline: working set per stage stays L2-resident
    for (int r = 0; r < RR; r++) {
        const int* ei_r  = ei + (size_t)r * 2 * EE;
        const int* dst_r = ei_r + EE;
        const float* ea_r = ea + (size_t)r * EE * FF;

        gather_kernel<<<EE, 256>>>(x, ei_r, ea_r);
        // kv = kvin @ [Wk|Wv] + [bk|bv]   (fused, Nc=512)
        run_gemm(kvin_h, kvin_l, KVIN, 0,
                 Wkv_h + (size_t)r * KVIN * 512, Wkv_l + (size_t)r * KVIN * 512,
                 512, 0, p_bkv + r * 512, 0,
                 p_kvb, 512, 0, nullptr, nullptr, 0, 0,
                 EE, 512, KVIN, 0, 1);
        // q = xdst @ Wq + bq
        run_gemm(xdst_h, xdst_l, HH, 0,
                 Wq_h + (size_t)r * HH * HH, Wq_l + (size_t)r * HH * HH,
                 HH, 0, bq + r * HH, 0,
                 p_qb, HH, 0, nullptr, nullptr, 0, 0,
                 EE, HH, HH, 0, 1);
        init_kernel<<<NN, 256>>>();
        score_kernel<<<EE, 256>>>(dst_r, prior + r * NHH);
        ex_kernel<<<(EE * NHH) / 256, 256>>>(dst_r);
        scatter_kernel<<<EE, 64>>>(dst_r);
        run_split(p_agg, agg_h, agg_l, NN * HH);
        // rel_out[r] = gelu(agg @ Wm + bm) -> column slice r*H of [N, R*H]
        run_gemm(agg_h, agg_l, HH, 0,
                 Wm_h + (size_t)r * HH * HH, Wm_l + (size_t)r * HH * HH,
                 HH, 0, bm + r * HH, 0,
                 p_relout + r * HH, RR * HH, 0,
                 relout_h + r * HH, relout_l + r * HH, RR * HH, 0,
                 NN, HH, HH, 1, 1);
    }

    // h = gelu(all_rel @ W_ir1 + b_ir1)
    run_gemm(relout_h, relout_l, RR * HH, 0, Wir1_h, Wir1_l, HH, 0,
             bir1, 0, p_h, HH, 0, nullptr, nullptr, 0, 0,
             NN, HH, RR * HH, 1, 1);
    inter_kernel<<<NN, 256>>>(Wir2, bir2);
    // stacked[p] = paths[p] @ Wmp[p] + bmp[p]
    run_gemm(paths_h, paths_l, 3 * HH, HH,
             Wmp_h, Wmp_l, HH, (long long)HH * HH,
             bmp, HH,
             p_stacked, 3 * HH, HH,
             stacked_h, stacked_l, 3 * HH, HH,
             NN, HH, HH, 0, 3);
    // t = tanh(stacked @ Wa1 + ba1)
    run_gemm(stacked_h, stacked_l, HH, 0, Wa1_h, Wa1_l, HH / 2, 0,
             ba1, 0, p_t, HH / 2, 0, nullptr, nullptr, 0, 0,
             3 * NN, HH / 2, HH, 2, 1);
    meta_kernel<<<NN, 256>>>(Wa2, gme, bme);
    // combined = gelu([inter_agg, meta] @ Wc + bc)
    run_gemm(combin_h, combin_l, 2 * HH, 0, Wc_h, Wc_l, HH, 0,
             bc, 0, p_comb, HH, 0, nullptr, nullptr, 0, 0,
             NN, HH, 2 * HH, 1, 1);
    final_kernel<<<NN, 256>>>(x, gout, bout, out);
}

// round 10
// speedup vs baseline: 1.2246x; 1.2246x over previous
#include <cuda_runtime.h>
#include <cuda_bf16.h>
#include <math.h>

#define NN 50000
#define RR 6
#define EE 32768
#define HH 256
#define FF 16
#define NHH 8
#define KVIN (HH + FF)      // 272

typedef __nv_bfloat16 bf16;

// ---------------- fp32 scratch (single relation; reused across loop) ------
__device__ float g_kb[EE * HH];
__device__ float g_vb[EE * HH];
__device__ float g_qb[EE * HH];
__device__ float g_scores[EE * NHH];
__device__ float g_denom[NN * NHH];
__device__ unsigned g_key[NN * NHH];
__device__ float g_agg[NN * HH];
__device__ float g_relout[(size_t)NN * RR * HH];    // [N, R*H]
__device__ float g_h[NN * HH];
__device__ float g_stacked[NN * 3 * HH];
__device__ float g_t[NN * 3 * (HH / 2)];
__device__ float g_interagg[NN * HH];
__device__ float g_comb[NN * HH];

// ---------------- bf16 hi/lo planes (activations) ----------------
__device__ bf16 g_x_h[NN * HH],      g_x_l[NN * HH];          // pre-split x
__device__ bf16 g_ea_h[RR * EE * FF], g_ea_l[RR * EE * FF];   // pre-split edge_attr
__device__ bf16 g_agg_h[NN * HH],    g_agg_l[NN * HH];
__device__ bf16 g_relout_h[(size_t)NN * RR * HH],  g_relout_l[(size_t)NN * RR * HH];
__device__ bf16 g_paths_h[NN * 3 * HH],   g_paths_l[NN * 3 * HH];
__device__ bf16 g_stacked_h[NN * 3 * HH], g_stacked_l[NN * 3 * HH];
__device__ bf16 g_combin_h[NN * 2 * HH],  g_combin_l[NN * 2 * HH];

// ---------------- bf16 hi/lo planes (weights) ----------------
__device__ bf16 g_Wq_h[RR * HH * HH],   g_Wq_l[RR * HH * HH];
__device__ bf16 g_Wk_h[RR * KVIN * HH], g_Wk_l[RR * KVIN * HH];
__device__ bf16 g_Wv_h[RR * KVIN * HH], g_Wv_l[RR * KVIN * HH];
__device__ bf16 g_Wm_h[RR * HH * HH],   g_Wm_l[RR * HH * HH];
__device__ bf16 g_Wir1_h[RR * HH * HH], g_Wir1_l[RR * HH * HH];
__device__ bf16 g_Wmp_h[3 * HH * HH],   g_Wmp_l[3 * HH * HH];
__device__ bf16 g_Wa1_h[HH * HH / 2],   g_Wa1_l[HH * HH / 2];
__device__ bf16 g_Wc_h[2 * HH * HH],    g_Wc_l[2 * HH * HH];

__device__ __forceinline__ float gelu_exact(float x) {
    return 0.5f * x * (1.0f + erff(x * 0.70710678118654752f));
}
__device__ __forceinline__ void split2(float v, bf16& hi, bf16& lo) {
    hi = __float2bfloat16(v);
    lo = __float2bfloat16(v - __bfloat162float(hi));
}
__device__ __forceinline__ unsigned enc_f(float f) {
    unsigned b = __float_as_uint(f);
    return (b & 0x80000000u) ? ~b : (b | 0x80000000u);
}
__device__ __forceinline__ float dec_f(unsigned u) {
    return (u & 0x80000000u) ? __uint_as_float(u ^ 0x80000000u)
                             : __uint_as_float(~u);
}

// ================= tensor-core GEMM (bf16 split, cp.async 4-stage) ========
// Optional row-gather on A (ridx) + secondary A source for cols >= HH
// (A2, row stride FF, row index = raw row) to feed [x[src] | edge_attr].
#define RS_A 24
#define RS_B 136
#define STAGE_BYTES 20992   // Ahi 6144 | Alo 6144 | Bhi 4352 | Blo 4352
#define GEMM_SMEM (4 * STAGE_BYTES)

__device__ __forceinline__ void cp16(unsigned d, const void* s, unsigned sz) {
    asm volatile("cp.async.cg.shared.global [%0], [%1], 16, %2;"
                 :: "r"(d), "l"(s), "r"(sz));
}
__device__ __forceinline__ void ldsm_x4(unsigned& r0, unsigned& r1,
                                        unsigned& r2, unsigned& r3,
                                        unsigned addr) {
    asm volatile("ldmatrix.sync.aligned.m8n8.x4.shared.b16 {%0,%1,%2,%3}, [%4];"
                 : "=r"(r0), "=r"(r1), "=r"(r2), "=r"(r3) : "r"(addr));
}
__device__ __forceinline__ void ldsm_x4t(unsigned& r0, unsigned& r1,
                                         unsigned& r2, unsigned& r3,
                                         unsigned addr) {
    asm volatile("ldmatrix.sync.aligned.m8n8.x4.trans.shared.b16 {%0,%1,%2,%3}, [%4];"
                 : "=r"(r0), "=r"(r1), "=r"(r2), "=r"(r3) : "r"(addr));
}
__device__ __forceinline__ void mma16816(float* c, const unsigned* a,
                                         unsigned b0, unsigned b1) {
    asm volatile(
        "mma.sync.aligned.m16n8k16.row.col.f32.bf16.bf16.f32 "
        "{%0,%1,%2,%3},{%4,%5,%6,%7},{%8,%9},{%0,%1,%2,%3};"
        : "+f"(c[0]), "+f"(c[1]), "+f"(c[2]), "+f"(c[3])
        : "r"(a[0]), "r"(a[1]), "r"(a[2]), "r"(a[3]), "r"(b0), "r"(b1));
}

// NOTE: no min-blocks clause — 128-reg cap forces spills (R4 regression).
__global__ __launch_bounds__(256)
void mma_gemm(const bf16* __restrict__ Ahi, const bf16* __restrict__ Alo,
              int lda, long long sA,
              const int* __restrict__ ridx,
              const bf16* __restrict__ A2hi, const bf16* __restrict__ A2lo,
              const bf16* __restrict__ Bhi, const bf16* __restrict__ Blo,
              int ldb, long long sB,
              const float* __restrict__ bias, int sBias,
              float* __restrict__ C, int ldc, long long sC,
              bf16* __restrict__ Chi, bf16* __restrict__ Clo,
              int ldc2, long long sC2,
              int M, int Nc, int K, int act)
{
    extern __shared__ __align__(128) char smem[];
    const unsigned smemBase = (unsigned)__cvta_generic_to_shared(smem);

    const int z = blockIdx.z;
    Ahi += (size_t)z * sA;  Alo += (size_t)z * sA;
    Bhi += (size_t)z * sB;  Blo += (size_t)z * sB;
    bias += (size_t)z * sBias;
    C += (size_t)z * sC;
    if (Chi) { Chi += (size_t)z * sC2; Clo += (size_t)z * sC2; }

    const int tid = threadIdx.x;
    const int lane = tid & 31;
    const int w = tid >> 5;
    const int wm = w & 3;
    const int wn = w >> 2;
    const int rowBase = blockIdx.y * 128;
    const int colBase = blockIdx.x * 128;
    const int nChunks = K >> 4;

    float acc[2][8][4];
#pragma unroll
    for (int i = 0; i < 2; i++)
#pragma unroll
        for (int j = 0; j < 8; j++)
#pragma unroll
            for (int q = 0; q < 4; q++) acc[i][j][q] = 0.0f;

    unsigned offA[2], offB[4];
#pragma unroll
    for (int mt = 0; mt < 2; mt++)
        offA[mt] = (wm * 32 + mt * 16 + (lane & 15)) * RS_A + (lane >> 4) * 8;
#pragma unroll
    for (int g = 0; g < 4; g++)
        offB[g] = (lane & 15) * RS_B + wn * 64 + g * 16 + (lane >> 4) * 8;

    const int aRow = tid >> 1;
    const int aCh  = (tid & 1) << 3;
    const int bRow = tid >> 4;
    const int bCh  = (tid & 15) << 3;
    const int rIdx = rowBase + aRow;
    const bool rOK = rIdx < M;
    const int gRow = rOK ? (ridx ? ridx[rIdx] : rIdx) : 0;
    const bf16* aRowH = Ahi + (size_t)gRow * lda;
    const bf16* aRowL = Alo + (size_t)gRow * lda;
    const bf16* a2H = A2hi ? A2hi + (size_t)rIdx * FF : nullptr;
    const bf16* a2L = A2hi ? A2lo + (size_t)rIdx * FF : nullptr;
    const unsigned aSz = rOK ? 16u : 0u;

    auto issue_stage = [&](int c) {
        if (c < nChunks) {
            const int k0 = c << 4;
            const unsigned sb = smemBase + (c & 3) * STAGE_BYTES;
            unsigned da = sb + (aRow * RS_A + aCh) * 2;
            if (a2H == nullptr || k0 < HH) {
                cp16(da,        aRowH + k0 + aCh, aSz);
                cp16(da + 6144, aRowL + k0 + aCh, aSz);
            } else {
                cp16(da,        a2H + (k0 - HH) + aCh, aSz);
                cp16(da + 6144, a2L + (k0 - HH) + aCh, aSz);
            }
            size_t bo = (size_t)(k0 + bRow) * ldb + colBase + bCh;
            unsigned db = sb + 12288 + (bRow * RS_B + bCh) * 2;
            cp16(db,        Bhi + bo, 16u);
            cp16(db + 4352, Blo + bo, 16u);
        }
        asm volatile("cp.async.commit_group;" ::);
    };

    issue_stage(0); issue_stage(1); issue_stage(2);

    for (int k = 0; k < nChunks; k++) {
        asm volatile("cp.async.wait_group 2;" ::);
        __syncthreads();
        issue_stage(k + 3);

        const unsigned sb = smemBase + (k & 3) * STAGE_BYTES;
        unsigned ah[2][4], al[2][4];
#pragma unroll
        for (int mt = 0; mt < 2; mt++) {
            ldsm_x4(ah[mt][0], ah[mt][1], ah[mt][2], ah[mt][3], sb + offA[mt] * 2);
            ldsm_x4(al[mt][0], al[mt][1], al[mt][2], al[mt][3], sb + 6144 + offA[mt] * 2);
        }
#pragma unroll
        for (int g = 0; g < 4; g++) {
            unsigned bh[4], bl[4];
            ldsm_x4t(bh[0], bh[1], bh[2], bh[3], sb + 12288 + offB[g] * 2);
            ldsm_x4t(bl[0], bl[1], bl[2], bl[3], sb + 16640 + offB[g] * 2);
#pragma unroll
            for (int mt = 0; mt < 2; mt++) {
                float* a0 = acc[mt][g * 2];
                float* a1 = acc[mt][g * 2 + 1];
                mma16816(a0, ah[mt], bh[0], bh[1]);
                mma16816(a0, ah[mt], bl[0], bl[1]);
                mma16816(a0, al[mt], bh[0], bh[1]);
                mma16816(a1, ah[mt], bh[2], bh[3]);
                mma16816(a1, ah[mt], bl[2], bl[3]);
                mma16816(a1, al[mt], bh[2], bh[3]);
            }
        }
    }

#pragma unroll
    for (int mt = 0; mt < 2; mt++) {
        int r0 = rowBase + wm * 32 + mt * 16 + (lane >> 2);
#pragma unroll
        for (int half = 0; half < 2; half++) {
            int r = r0 + half * 8;
            if (r >= M) continue;
#pragma unroll
            for (int nt = 0; nt < 8; nt++) {
                int cg = colBase + wn * 64 + nt * 8 + (lane & 3) * 2;
                float v0 = acc[mt][nt][half * 2]     + bias[cg];
                float v1 = acc[mt][nt][half * 2 + 1] + bias[cg + 1];
                if (act == 1) { v0 = gelu_exact(v0); v1 = gelu_exact(v1); }
                else if (act == 2) { v0 = tanhf(v0); v1 = tanhf(v1); }
                *(float2*)&C[(size_t)r * ldc + cg] = make_float2(v0, v1);
                if (Chi) {
                    bf16 h0, l0, h1, l1;
                    split2(v0, h0, l0); split2(v1, h1, l1);
                    __nv_bfloat162 ph; ph.x = h0; ph.y = h1;
                    __nv_bfloat162 pl; pl.x = l0; pl.y = l1;
                    *(__nv_bfloat162*)&Chi[(size_t)r * ldc2 + cg] = ph;
                    *(__nv_bfloat162*)&Clo[(size_t)r * ldc2 + cg] = pl;
                }
            }
        }
    }
}

// ---------------- elementwise helpers ----------------
__global__ void split_kernel(const float* __restrict__ src,
                             bf16* __restrict__ hi, bf16* __restrict__ lo, int n)
{
    int i = blockIdx.x * 256 + threadIdx.x;
    if (i < n) split2(src[i], hi[i], lo[i]);
}

// ---------------- per-relation kernels (R3 versions) ----------------
__global__ void init_kernel()
{
    int idx = blockIdx.x * 256 + threadIdx.x;   // grid = NN blocks
    g_agg[idx] = 0.0f;
    if (idx < NN * NHH) { g_denom[idx] = 0.0f; g_key[idx] = 0u; }
}

__global__ void score_kernel(const int* __restrict__ dst_r,
                             const float* __restrict__ prior_r)
{
    int e = blockIdx.x, t = threadIdx.x;
    int h = t >> 5, lane = t & 31;
    float p = g_qb[e * HH + t] * g_kb[e * HH + t];
#pragma unroll
    for (int o = 16; o > 0; o >>= 1) p += __shfl_down_sync(0xFFFFFFFFu, p, o);
    if (lane == 0) {
        int dst = dst_r[e];
        float s = p * 0.17677669529663689f * prior_r[h];
        g_scores[e * NHH + h] = s;
        atomicMax(&g_key[dst * NHH + h], enc_f(s));
    }
}

__global__ void ex_kernel(const int* __restrict__ dst_r)
{
    int idx = blockIdx.x * 256 + threadIdx.x;   // EE*NHH
    int e = idx >> 3, h = idx & 7;
    int dst = dst_r[e];
    float m = dec_f(g_key[dst * NHH + h]);
    float ex = expf(g_scores[idx] - m);
    g_scores[idx] = ex;
    atomicAdd(&g_denom[dst * NHH + h], ex);
}

__global__ void scatter_kernel(const int* __restrict__ dst_r)
{
    int e = blockIdx.x, t = threadIdx.x;   // 256 threads
    int h = t >> 5;
    int dst = dst_r[e];
    float w = g_scores[e * NHH + h] / (g_denom[dst * NHH + h] + 1e-16f);
    atomicAdd(&g_agg[(size_t)dst * HH + t], w * g_vb[e * HH + t]);
}

// ---------------- inter-relation fusion ----------------
__global__ void inter_kernel(const float* __restrict__ Wir2,
                             const float* __restrict__ bir2)
{
    int n = blockIdx.x, t = threadIdx.x;
    int w = t >> 5, lane = t & 31;
    __shared__ float logit[RR];
    if (w < RR) {
        float s = 0.0f;
        for (int i = lane; i < HH; i += 32)
            s += g_h[(size_t)n * HH + i] * Wir2[i * RR + w];
#pragma unroll
        for (int o = 16; o > 0; o >>= 1) s += __shfl_down_sync(0xFFFFFFFFu, s, o);
        if (lane == 0) logit[w] = s + bir2[w];
    }
    __syncthreads();
    float l[RR]; float mx = -1e30f;
#pragma unroll
    for (int r = 0; r < RR; r++) { l[r] = logit[r]; mx = fmaxf(mx, l[r]); }
    float sum = 0.0f;
#pragma unroll
    for (int r = 0; r < RR; r++) { l[r] = expf(l[r] - mx); sum += l[r]; }
    float inv = 1.0f / sum;
    int c = t;
    const float* ro = g_relout + (size_t)n * (RR * HH);
    float acc = 0.0f;
#pragma unroll
    for (int r = 0; r < RR; r++) acc += l[r] * inv * ro[r * HH + c];
    g_interagg[(size_t)n * HH + c] = acc;
    size_t base = (size_t)n * 3 * HH;
    split2(ro[2 * HH + c] + ro[3 * HH + c], g_paths_h[base + c],          g_paths_l[base + c]);
    split2(ro[4 * HH + c] + ro[0 * HH + c], g_paths_h[base + HH + c],     g_paths_l[base + HH + c]);
    split2(ro[1 * HH + c] + ro[5 * HH + c], g_paths_h[base + 2 * HH + c], g_paths_l[base + 2 * HH + c]);
}

__global__ void meta_kernel(const float* __restrict__ Wa2,
                            const float* __restrict__ gm,
                            const float* __restrict__ bm_)
{
    int n = blockIdx.x, t = threadIdx.x;
    int w = t >> 5, lane = t & 31;
    __shared__ float sl[3];
    __shared__ float red[HH];
    __shared__ float s_mu, s_var;
    if (w < 3) {
        float s = 0.0f;
        for (int i = lane; i < HH / 2; i += 32)
            s += g_t[((size_t)n * 3 + w) * (HH / 2) + i] * Wa2[i];
#pragma unroll
        for (int o = 16; o > 0; o >>= 1) s += __shfl_down_sync(0xFFFFFFFFu, s, o);
        if (lane == 0) sl[w] = s;
    }
    __syncthreads();
    float a0 = sl[0], a1 = sl[1], a2 = sl[2];
    float mx = fmaxf(a0, fmaxf(a1, a2));
    float e0 = expf(a0 - mx), e1 = expf(a1 - mx), e2 = expf(a2 - mx);
    float inv = 1.0f / (e0 + e1 + e2);
    int c = t;
    const float* st = g_stacked + (size_t)n * 3 * HH;
    float mpre = (e0 * st[c] + e1 * st[HH + c] + e2 * st[2 * HH + c]) * inv;
    red[t] = mpre; __syncthreads();
    for (int s = 128; s > 0; s >>= 1) { if (t < s) red[t] += red[t + s]; __syncthreads(); }
    if (t == 0) s_mu = red[0] * (1.0f / HH);
    __syncthreads();
    float d = mpre - s_mu;
    red[t] = d * d; __syncthreads();
    for (int s = 128; s > 0; s >>= 1) { if (t < s) red[t] += red[t + s]; __syncthreads(); }
    if (t == 0) s_var = red[0] * (1.0f / HH);
    __syncthreads();
    float meta = d * rsqrtf(s_var + 1e-5f) * gm[c] + bm_[c];
    size_t base = (size_t)n * 2 * HH;
    split2(g_interagg[(size_t)n * HH + c], g_combin_h[base + c],      g_combin_l[base + c]);
    split2(meta,                           g_combin_h[base + HH + c], g_combin_l[base + HH + c]);
}

__global__ void final_kernel(const float* __restrict__ x,
                             const float* __restrict__ g,
                             const float* __restrict__ b,
                             float* __restrict__ out)
{
    int n = blockIdx.x, t = threadIdx.x;
    __shared__ float red[HH];
    __shared__ float s_mu, s_var;
    float v = x[(size_t)n * HH + t] + g_comb[(size_t)n * HH + t];
    red[t] = v; __syncthreads();
    for (int s = 128; s > 0; s >>= 1) { if (t < s) red[t] += red[t + s]; __syncthreads(); }
    if (t == 0) s_mu = red[0] * (1.0f / HH);
    __syncthreads();
    float d = v - s_mu;
    red[t] = d * d; __syncthreads();
    for (int s = 128; s > 0; s >>= 1) { if (t < s) red[t] += red[t + s]; __syncthreads(); }
    if (t == 0) s_var = red[0] * (1.0f / HH);
    __syncthreads();
    out[(size_t)n * HH + t] = d * rsqrtf(s_var + 1e-5f) * g[t] + b[t];
}

// ---------------- host ----------------
static inline void run_gemm(const bf16* Ah, const bf16* Al, int lda, long long sA,
                            const int* ridx, const bf16* A2h, const bf16* A2l,
                            const bf16* Bh, const bf16* Bl, int ldb, long long sB,
                            const float* bias, int sBias,
                            float* C, int ldc, long long sC,
                            bf16* Ch, bf16* Cl, int ldc2, long long sC2,
                            int M, int Nc, int K, int act, int Z)
{
    dim3 grid(Nc / 128, (M + 127) / 128, Z);
    mma_gemm<<<grid, 256, GEMM_SMEM>>>(Ah, Al, lda, sA, ridx, A2h, A2l,
                                       Bh, Bl, ldb, sB, bias, sBias,
                                       C, ldc, sC, Ch, Cl, ldc2, sC2,
                                       M, Nc, K, act);
}
static inline void run_split(const float* src, bf16* hi, bf16* lo, size_t n)
{
    split_kernel<<<(unsigned)((n + 255) / 256), 256>>>(src, hi, lo, (int)n);
}

extern "C" void kernel_launch(void* const* d_in, const int* in_sizes, int n_in,
                              void* d_out, int out_size)
{
    const float* x    = (const float*)d_in[0];
    const int*   ei   = (const int*)d_in[1];
    const float* ea   = (const float*)d_in[2];
    const float* Wq   = (const float*)d_in[3];
    const float* bq   = (const float*)d_in[4];
    const float* Wk   = (const float*)d_in[5];
    const float* bk   = (const float*)d_in[6];
    const float* Wv   = (const float*)d_in[7];
    const float* bv   = (const float*)d_in[8];
    const float* prior= (const float*)d_in[9];
    const float* Wm   = (const float*)d_in[10];
    const float* bm   = (const float*)d_in[11];
    const float* Wir1 = (const float*)d_in[12];
    const float* bir1 = (const float*)d_in[13];
    const float* Wir2 = (const float*)d_in[14];
    const float* bir2 = (const float*)d_in[15];
    const float* Wmp  = (const float*)d_in[16];
    const float* bmp  = (const float*)d_in[17];
    const float* Wa1  = (const float*)d_in[18];
    const float* ba1  = (const float*)d_in[19];
    const float* Wa2  = (const float*)d_in[20];
    const float* gme  = (const float*)d_in[21];
    const float* bme  = (const float*)d_in[22];
    const float* Wc   = (const float*)d_in[23];
    const float* bc   = (const float*)d_in[24];
    const float* gout = (const float*)d_in[25];
    const float* bout = (const float*)d_in[26];
    float* out = (float*)d_out;

    cudaFuncSetAttribute(mma_gemm,
                         cudaFuncAttributeMaxDynamicSharedMemorySize, GEMM_SMEM);

#define SYM(p, s) { void* tmp; cudaGetSymbolAddress(&tmp, s); p = (decltype(p))tmp; }
    float *p_kb, *p_vb, *p_qb, *p_agg, *p_relout, *p_h, *p_stacked, *p_t, *p_comb;
    SYM(p_kb, g_kb); SYM(p_vb, g_vb); SYM(p_qb, g_qb); SYM(p_agg, g_agg);
    SYM(p_relout, g_relout); SYM(p_h, g_h); SYM(p_stacked, g_stacked);
    SYM(p_t, g_t); SYM(p_comb, g_comb);
    bf16 *x_h, *x_l, *ea_h, *ea_l, *agg_h, *agg_l,
         *relout_h, *relout_l, *paths_h, *paths_l, *stacked_h, *stacked_l,
         *combin_h, *combin_l;
    SYM(x_h, g_x_h);   SYM(x_l, g_x_l);
    SYM(ea_h, g_ea_h); SYM(ea_l, g_ea_l);
    SYM(agg_h, g_agg_h);   SYM(agg_l, g_agg_l);
    SYM(relout_h, g_relout_h); SYM(relout_l, g_relout_l);
    SYM(paths_h, g_paths_h);   SYM(paths_l, g_paths_l);
    SYM(stacked_h, g_stacked_h); SYM(stacked_l, g_stacked_l);
    SYM(combin_h, g_combin_h);   SYM(combin_l, g_combin_l);
    bf16 *Wq_h, *Wq_l, *Wk_h, *Wk_l, *Wv_h, *Wv_l, *Wm_h, *Wm_l,
         *Wir1_h, *Wir1_l, *Wmp_h, *Wmp_l, *Wa1_h, *Wa1_l, *Wc_h, *Wc_l;
    SYM(Wq_h, g_Wq_h); SYM(Wq_l, g_Wq_l);
    SYM(Wk_h, g_Wk_h); SYM(Wk_l, g_Wk_l);
    SYM(Wv_h, g_Wv_h); SYM(Wv_l, g_Wv_l);
    SYM(Wm_h, g_Wm_h); SYM(Wm_l, g_Wm_l);
    SYM(Wir1_h, g_Wir1_h); SYM(Wir1_l, g_Wir1_l);
    SYM(Wmp_h, g_Wmp_h);   SYM(Wmp_l, g_Wmp_l);
    SYM(Wa1_h, g_Wa1_h);   SYM(Wa1_l, g_Wa1_l);
    SYM(Wc_h, g_Wc_h);     SYM(Wc_l, g_Wc_l);
#undef SYM

    // one-time splits: x, edge_attr, weights
    run_split(x,    x_h,    x_l,    NN * HH);
    run_split(ea,   ea_h,   ea_l,   RR * EE * FF);
    run_split(Wq,   Wq_h,   Wq_l,   RR * HH * HH);
    run_split(Wk,   Wk_h,   Wk_l,   RR * KVIN * HH);
    run_split(Wv,   Wv_h,   Wv_l,   RR * KVIN * HH);
    run_split(Wm,   Wm_h,   Wm_l,   RR * HH * HH);
    run_split(Wir1, Wir1_h, Wir1_l, RR * HH * HH);
    run_split(Wmp,  Wmp_h,  Wmp_l,  3 * HH * HH);
    run_split(Wa1,  Wa1_h,  Wa1_l,  HH * HH / 2);
    run_split(Wc,   Wc_h,   Wc_l,   2 * HH * HH);

    // per-relation pipeline (R3 structure, gather fused into GEMM A-path)
    for (int r = 0; r < RR; r++) {
        const int* ei_r  = ei + (size_t)r * 2 * EE;
        const int* src_r = ei_r;
        const int* dst_r = ei_r + EE;
        const bf16* ea_h_r = ea_h + (size_t)r * EE * FF;
        const bf16* ea_l_r = ea_l + (size_t)r * EE * FF;

        // k = [x[src] | ea] @ Wk + bk   (A gathered via src, tail from ea)
        run_gemm(x_h, x_l, HH, 0, src_r, ea_h_r, ea_l_r,
                 Wk_h + (size_t)r * KVIN * HH, Wk_l + (size_t)r * KVIN * HH,
                 HH, 0, bk + r * HH, 0,
                 p_kb, HH, 0, nullptr, nullptr, 0, 0,
                 EE, HH, KVIN, 0, 1);
        // v = [x[src] | ea] @ Wv + bv
        run_gemm(x_h, x_l, HH, 0, src_r, ea_h_r, ea_l_r,
                 Wv_h + (size_t)r * KVIN * HH, Wv_l + (size_t)r * KVIN * HH,
                 HH, 0, bv + r * HH, 0,
                 p_vb, HH, 0, nullptr, nullptr, 0, 0,
                 EE, HH, KVIN, 0, 1);
        // q = x[dst] @ Wq + bq
        run_gemm(x_h, x_l, HH, 0, dst_r, nullptr, nullptr,
                 Wq_h + (size_t)r * HH * HH, Wq_l + (size_t)r * HH * HH,
                 HH, 0, bq + r * HH, 0,
                 p_qb, HH, 0, nullptr, nullptr, 0, 0,
                 EE, HH, HH, 0, 1);
        init_kernel<<<NN, 256>>>();
        score_kernel<<<EE, 256>>>(dst_r, prior + r * NHH);
        ex_kernel<<<(EE * NHH) / 256, 256>>>(dst_r);
        scatter_kernel<<<EE, 256>>>(dst_r);
        run_split(p_agg, agg_h, agg_l, NN * HH);
        // rel_out[r] = gelu(agg @ Wm + bm) -> column slice r*H of [N, R*H]
        run_gemm(agg_h, agg_l, HH, 0, nullptr, nullptr, nullptr,
                 Wm_h + (size_t)r * HH * HH, Wm_l + (size_t)r * HH * HH,
                 HH, 0, bm + r * HH, 0,
                 p_relout + r * HH, RR * HH, 0,
                 relout_h + r * HH, relout_l + r * HH, RR * HH, 0,
                 NN, HH, HH, 1, 1);
    }

    // h = gelu(all_rel @ W_ir1 + b_ir1)
    run_gemm(relout_h, relout_l, RR * HH, 0, nullptr, nullptr, nullptr,
             Wir1_h, Wir1_l, HH, 0, bir1, 0,
             p_h, HH, 0, nullptr, nullptr, 0, 0,
             NN, HH, RR * HH, 1, 1);
    inter_kernel<<<NN, 256>>>(Wir2, bir2);
    // stacked[p] = paths[p] @ Wmp[p] + bmp[p]
    run_gemm(paths_h, paths_l, 3 * HH, HH, nullptr, nullptr, nullptr,
             Wmp_h, Wmp_l, HH, (long long)HH * HH, bmp, HH,
             p_stacked, 3 * HH, HH,
             stacked_h, stacked_l, 3 * HH, HH,
             NN, HH, HH, 0, 3);
    // t = tanh(stacked @ Wa1 + ba1)
    run_gemm(stacked_h, stacked_l, HH, 0, nullptr, nullptr, nullptr,
             Wa1_h, Wa1_l, HH / 2, 0, ba1, 0,
             p_t, HH / 2, 0, nullptr, nullptr, 0, 0,
             3 * NN, HH / 2, HH, 2, 1);
    meta_kernel<<<NN, 256>>>(Wa2, gme, bme);
    // combined = gelu([inter_agg, meta] @ Wc + bc)
    run_gemm(combin_h, combin_l, 2 * HH, 0, nullptr, nullptr, nullptr,
             Wc_h, Wc_l, HH, 0, bc, 0,
             p_comb, HH, 0, nullptr, nullptr, 0, 0,
             NN, HH, 2 * HH, 1, 1);
    final_kernel<<<NN, 256>>>(x, gout, bout, out);
}

// round 11
// speedup vs baseline: 1.2819x; 1.0468x over previous
#include <cuda_runtime.h>
#include <cuda_bf16.h>
#include <math.h>

#define NN 50000
#define RR 6
#define EE 32768
#define HH 256
#define FF 16
#define NHH 8
#define KVIN (HH + FF)      // 272

typedef __nv_bfloat16 bf16;

// ---------------- fp32 scratch (single relation; reused across loop) ------
__device__ float g_kb[EE * HH];
__device__ float g_vb[EE * HH];
__device__ float g_qb[EE * HH];
__device__ float g_scores[EE * NHH];
__device__ float g_denom[NN * NHH];
__device__ float g_agg[NN * HH];
__device__ float g_relout[(size_t)NN * RR * HH];    // [N, R*H]
__device__ float g_h[NN * HH];
__device__ float g_stacked[NN * 3 * HH];
__device__ float g_t[NN * 3 * (HH / 2)];
__device__ float g_interagg[NN * HH];
__device__ float g_comb[NN * HH];

// ---------------- bf16 hi/lo planes (activations) ----------------
__device__ bf16 g_x_h[NN * HH],      g_x_l[NN * HH];          // pre-split x
__device__ bf16 g_ea_h[RR * EE * FF], g_ea_l[RR * EE * FF];   // pre-split edge_attr
__device__ bf16 g_agg_h[NN * HH],    g_agg_l[NN * HH];
__device__ bf16 g_relout_h[(size_t)NN * RR * HH],  g_relout_l[(size_t)NN * RR * HH];
__device__ bf16 g_paths_h[NN * 3 * HH],   g_paths_l[NN * 3 * HH];
__device__ bf16 g_stacked_h[NN * 3 * HH], g_stacked_l[NN * 3 * HH];
__device__ bf16 g_combin_h[NN * 2 * HH],  g_combin_l[NN * 2 * HH];

// ---------------- bf16 hi/lo planes (weights) ----------------
__device__ bf16 g_Wq_h[RR * HH * HH],   g_Wq_l[RR * HH * HH];
__device__ bf16 g_Wk_h[RR * KVIN * HH], g_Wk_l[RR * KVIN * HH];
__device__ bf16 g_Wv_h[RR * KVIN * HH], g_Wv_l[RR * KVIN * HH];
__device__ bf16 g_Wm_h[RR * HH * HH],   g_Wm_l[RR * HH * HH];
__device__ bf16 g_Wir1_h[RR * HH * HH], g_Wir1_l[RR * HH * HH];
__device__ bf16 g_Wmp_h[3 * HH * HH],   g_Wmp_l[3 * HH * HH];
__device__ bf16 g_Wa1_h[HH * HH / 2],   g_Wa1_l[HH * HH / 2];
__device__ bf16 g_Wc_h[2 * HH * HH],    g_Wc_l[2 * HH * HH];

__device__ __forceinline__ float gelu_exact(float x) {
    return 0.5f * x * (1.0f + erff(x * 0.70710678118654752f));
}
__device__ __forceinline__ void split2(float v, bf16& hi, bf16& lo) {
    hi = __float2bfloat16(v);
    lo = __float2bfloat16(v - __bfloat162float(hi));
}

// ================= tensor-core GEMM (bf16 split, cp.async 4-stage) ========
// Optional row-gather on A (ridx) + secondary A source for cols >= HH
// (A2, row stride FF, row index = raw row) to feed [x[src] | edge_attr].
#define RS_A 24
#define RS_B 136
#define STAGE_BYTES 20992   // Ahi 6144 | Alo 6144 | Bhi 4352 | Blo 4352
#define GEMM_SMEM (4 * STAGE_BYTES)

__device__ __forceinline__ void cp16(unsigned d, const void* s, unsigned sz) {
    asm volatile("cp.async.cg.shared.global [%0], [%1], 16, %2;"
                 :: "r"(d), "l"(s), "r"(sz));
}
__device__ __forceinline__ void ldsm_x4(unsigned& r0, unsigned& r1,
                                        unsigned& r2, unsigned& r3,
                                        unsigned addr) {
    asm volatile("ldmatrix.sync.aligned.m8n8.x4.shared.b16 {%0,%1,%2,%3}, [%4];"
                 : "=r"(r0), "=r"(r1), "=r"(r2), "=r"(r3) : "r"(addr));
}
__device__ __forceinline__ void ldsm_x4t(unsigned& r0, unsigned& r1,
                                         unsigned& r2, unsigned& r3,
                                         unsigned addr) {
    asm volatile("ldmatrix.sync.aligned.m8n8.x4.trans.shared.b16 {%0,%1,%2,%3}, [%4];"
                 : "=r"(r0), "=r"(r1), "=r"(r2), "=r"(r3) : "r"(addr));
}
__device__ __forceinline__ void mma16816(float* c, const unsigned* a,
                                         unsigned b0, unsigned b1) {
    asm volatile(
        "mma.sync.aligned.m16n8k16.row.col.f32.bf16.bf16.f32 "
        "{%0,%1,%2,%3},{%4,%5,%6,%7},{%8,%9},{%0,%1,%2,%3};"
        : "+f"(c[0]), "+f"(c[1]), "+f"(c[2]), "+f"(c[3])
        : "r"(a[0]), "r"(a[1]), "r"(a[2]), "r"(a[3]), "r"(b0), "r"(b1));
}

// NOTE: no min-blocks clause — 128-reg cap forces spills (R4 regression).
__global__ __launch_bounds__(256)
void mma_gemm(const bf16* __restrict__ Ahi, const bf16* __restrict__ Alo,
              int lda, long long sA,
              const int* __restrict__ ridx,
              const bf16* __restrict__ A2hi, const bf16* __restrict__ A2lo,
              const bf16* __restrict__ Bhi, const bf16* __restrict__ Blo,
              int ldb, long long sB,
              const float* __restrict__ bias, int sBias,
              float* __restrict__ C, int ldc, long long sC,
              bf16* __restrict__ Chi, bf16* __restrict__ Clo,
              int ldc2, long long sC2,
              int M, int Nc, int K, int act)
{
    extern __shared__ __align__(128) char smem[];
    const unsigned smemBase = (unsigned)__cvta_generic_to_shared(smem);

    const int z = blockIdx.z;
    Ahi += (size_t)z * sA;  Alo += (size_t)z * sA;
    Bhi += (size_t)z * sB;  Blo += (size_t)z * sB;
    bias += (size_t)z * sBias;
    C += (size_t)z * sC;
    if (Chi) { Chi += (size_t)z * sC2; Clo += (size_t)z * sC2; }

    const int tid = threadIdx.x;
    const int lane = tid & 31;
    const int w = tid >> 5;
    const int wm = w & 3;
    const int wn = w >> 2;
    const int rowBase = blockIdx.y * 128;
    const int colBase = blockIdx.x * 128;
    const int nChunks = K >> 4;

    float acc[2][8][4];
#pragma unroll
    for (int i = 0; i < 2; i++)
#pragma unroll
        for (int j = 0; j < 8; j++)
#pragma unroll
            for (int q = 0; q < 4; q++) acc[i][j][q] = 0.0f;

    unsigned offA[2], offB[4];
#pragma unroll
    for (int mt = 0; mt < 2; mt++)
        offA[mt] = (wm * 32 + mt * 16 + (lane & 15)) * RS_A + (lane >> 4) * 8;
#pragma unroll
    for (int g = 0; g < 4; g++)
        offB[g] = (lane & 15) * RS_B + wn * 64 + g * 16 + (lane >> 4) * 8;

    const int aRow = tid >> 1;
    const int aCh  = (tid & 1) << 3;
    const int bRow = tid >> 4;
    const int bCh  = (tid & 15) << 3;
    const int rIdx = rowBase + aRow;
    const bool rOK = rIdx < M;
    const int gRow = rOK ? (ridx ? ridx[rIdx] : rIdx) : 0;
    const bf16* aRowH = Ahi + (size_t)gRow * lda;
    const bf16* aRowL = Alo + (size_t)gRow * lda;
    const bf16* a2H = A2hi ? A2hi + (size_t)rIdx * FF : nullptr;
    const bf16* a2L = A2hi ? A2lo + (size_t)rIdx * FF : nullptr;
    const unsigned aSz = rOK ? 16u : 0u;

    auto issue_stage = [&](int c) {
        if (c < nChunks) {
            const int k0 = c << 4;
            const unsigned sb = smemBase + (c & 3) * STAGE_BYTES;
            unsigned da = sb + (aRow * RS_A + aCh) * 2;
            if (a2H == nullptr || k0 < HH) {
                cp16(da,        aRowH + k0 + aCh, aSz);
                cp16(da + 6144, aRowL + k0 + aCh, aSz);
            } else {
                cp16(da,        a2H + (k0 - HH) + aCh, aSz);
                cp16(da + 6144, a2L + (k0 - HH) + aCh, aSz);
            }
            size_t bo = (size_t)(k0 + bRow) * ldb + colBase + bCh;
            unsigned db = sb + 12288 + (bRow * RS_B + bCh) * 2;
            cp16(db,        Bhi + bo, 16u);
            cp16(db + 4352, Blo + bo, 16u);
        }
        asm volatile("cp.async.commit_group;" ::);
    };

    issue_stage(0); issue_stage(1); issue_stage(2);

    for (int k = 0; k < nChunks; k++) {
        asm volatile("cp.async.wait_group 2;" ::);
        __syncthreads();
        issue_stage(k + 3);

        const unsigned sb = smemBase + (k & 3) * STAGE_BYTES;
        unsigned ah[2][4], al[2][4];
#pragma unroll
        for (int mt = 0; mt < 2; mt++) {
            ldsm_x4(ah[mt][0], ah[mt][1], ah[mt][2], ah[mt][3], sb + offA[mt] * 2);
            ldsm_x4(al[mt][0], al[mt][1], al[mt][2], al[mt][3], sb + 6144 + offA[mt] * 2);
        }
#pragma unroll
        for (int g = 0; g < 4; g++) {
            unsigned bh[4], bl[4];
            ldsm_x4t(bh[0], bh[1], bh[2], bh[3], sb + 12288 + offB[g] * 2);
            ldsm_x4t(bl[0], bl[1], bl[2], bl[3], sb + 16640 + offB[g] * 2);
#pragma unroll
            for (int mt = 0; mt < 2; mt++) {
                float* a0 = acc[mt][g * 2];
                float* a1 = acc[mt][g * 2 + 1];
                mma16816(a0, ah[mt], bh[0], bh[1]);
                mma16816(a0, ah[mt], bl[0], bl[1]);
                mma16816(a0, al[mt], bh[0], bh[1]);
                mma16816(a1, ah[mt], bh[2], bh[3]);
                mma16816(a1, ah[mt], bl[2], bl[3]);
                mma16816(a1, al[mt], bh[2], bh[3]);
            }
        }
    }

#pragma unroll
    for (int mt = 0; mt < 2; mt++) {
        int r0 = rowBase + wm * 32 + mt * 16 + (lane >> 2);
#pragma unroll
        for (int half = 0; half < 2; half++) {
            int r = r0 + half * 8;
            if (r >= M) continue;
#pragma unroll
            for (int nt = 0; nt < 8; nt++) {
                int cg = colBase + wn * 64 + nt * 8 + (lane & 3) * 2;
                float v0 = acc[mt][nt][half * 2]     + bias[cg];
                float v1 = acc[mt][nt][half * 2 + 1] + bias[cg + 1];
                if (act == 1) { v0 = gelu_exact(v0); v1 = gelu_exact(v1); }
                else if (act == 2) { v0 = tanhf(v0); v1 = tanhf(v1); }
                *(float2*)&C[(size_t)r * ldc + cg] = make_float2(v0, v1);
                if (Chi) {
                    bf16 h0, l0, h1, l1;
                    split2(v0, h0, l0); split2(v1, h1, l1);
                    __nv_bfloat162 ph; ph.x = h0; ph.y = h1;
                    __nv_bfloat162 pl; pl.x = l0; pl.y = l1;
                    *(__nv_bfloat162*)&Chi[(size_t)r * ldc2 + cg] = ph;
                    *(__nv_bfloat162*)&Clo[(size_t)r * ldc2 + cg] = pl;
                }
            }
        }
    }
}

// ---------------- elementwise helpers ----------------
__global__ void split_kernel(const float* __restrict__ src,
                             bf16* __restrict__ hi, bf16* __restrict__ lo, int n)
{
    int i = blockIdx.x * 256 + threadIdx.x;
    if (i < n) split2(src[i], hi[i], lo[i]);
}

// ---------------- per-relation kernels ----------------
// zero agg + denom (once, before loop)
__global__ void init0_kernel()
{
    int n = blockIdx.x, t = threadIdx.x;
    g_agg[(size_t)n * HH + t] = 0.0f;
    if (t < NHH) g_denom[n * NHH + t] = 0.0f;
}

// score + exp + denom accumulation in one pass (no segment-max needed:
// scores are O(1) by construction; exp(s)/Σexp(s) == exp(s-m)/Σexp(s-m))
__global__ void score_kernel(const int* __restrict__ dst_r,
                             const float* __restrict__ prior_r)
{
    int e = blockIdx.x, t = threadIdx.x;
    int h = t >> 5, lane = t & 31;
    float p = g_qb[e * HH + t] * g_kb[e * HH + t];
#pragma unroll
    for (int o = 16; o > 0; o >>= 1) p += __shfl_down_sync(0xFFFFFFFFu, p, o);
    if (lane == 0) {
        int dst = dst_r[e];
        float ex = expf(p * 0.17677669529663689f * prior_r[h]);
        g_scores[e * NHH + h] = ex;
        atomicAdd(&g_denom[dst * NHH + h], ex);
    }
}

__global__ void scatter_kernel(const int* __restrict__ dst_r)
{
    int e = blockIdx.x, t = threadIdx.x;   // 256 threads
    int h = t >> 5;
    int dst = dst_r[e];
    float w = g_scores[e * NHH + h] / (g_denom[dst * NHH + h] + 1e-16f);
    atomicAdd(&g_agg[(size_t)dst * HH + t], w * g_vb[e * HH + t]);
}

// split agg to bf16 planes AND re-zero agg/denom for the next relation
__global__ void split_reset_kernel()
{
    int n = blockIdx.x, t = threadIdx.x;
    size_t idx = (size_t)n * HH + t;
    split2(g_agg[idx], g_agg_h[idx], g_agg_l[idx]);
    g_agg[idx] = 0.0f;
    if (t < NHH) g_denom[n * NHH + t] = 0.0f;
}

// ---------------- inter-relation fusion ----------------
__global__ void inter_kernel(const float* __restrict__ Wir2,
                             const float* __restrict__ bir2)
{
    int n = blockIdx.x, t = threadIdx.x;
    int w = t >> 5, lane = t & 31;
    __shared__ float logit[RR];
    if (w < RR) {
        float s = 0.0f;
        for (int i = lane; i < HH; i += 32)
            s += g_h[(size_t)n * HH + i] * Wir2[i * RR + w];
#pragma unroll
        for (int o = 16; o > 0; o >>= 1) s += __shfl_down_sync(0xFFFFFFFFu, s, o);
        if (lane == 0) logit[w] = s + bir2[w];
    }
    __syncthreads();
    float l[RR]; float mx = -1e30f;
#pragma unroll
    for (int r = 0; r < RR; r++) { l[r] = logit[r]; mx = fmaxf(mx, l[r]); }
    float sum = 0.0f;
#pragma unroll
    for (int r = 0; r < RR; r++) { l[r] = expf(l[r] - mx); sum += l[r]; }
    float inv = 1.0f / sum;
    int c = t;
    const float* ro = g_relout + (size_t)n * (RR * HH);
    float acc = 0.0f;
#pragma unroll
    for (int r = 0; r < RR; r++) acc += l[r] * inv * ro[r * HH + c];
    g_interagg[(size_t)n * HH + c] = acc;
    size_t base = (size_t)n * 3 * HH;
    split2(ro[2 * HH + c] + ro[3 * HH + c], g_paths_h[base + c],          g_paths_l[base + c]);
    split2(ro[4 * HH + c] + ro[0 * HH + c], g_paths_h[base + HH + c],     g_paths_l[base + HH + c]);
    split2(ro[1 * HH + c] + ro[5 * HH + c], g_paths_h[base + 2 * HH + c], g_paths_l[base + 2 * HH + c]);
}

__global__ void meta_kernel(const float* __restrict__ Wa2,
                            const float* __restrict__ gm,
                            const float* __restrict__ bm_)
{
    int n = blockIdx.x, t = threadIdx.x;
    int w = t >> 5, lane = t & 31;
    __shared__ float sl[3];
    __shared__ float red[HH];
    __shared__ float s_mu, s_var;
    if (w < 3) {
        float s = 0.0f;
        for (int i = lane; i < HH / 2; i += 32)
            s += g_t[((size_t)n * 3 + w) * (HH / 2) + i] * Wa2[i];
#pragma unroll
        for (int o = 16; o > 0; o >>= 1) s += __shfl_down_sync(0xFFFFFFFFu, s, o);
        if (lane == 0) sl[w] = s;
    }
    __syncthreads();
    float a0 = sl[0], a1 = sl[1], a2 = sl[2];
    float mx = fmaxf(a0, fmaxf(a1, a2));
    float e0 = expf(a0 - mx), e1 = expf(a1 - mx), e2 = expf(a2 - mx);
    float inv = 1.0f / (e0 + e1 + e2);
    int c = t;
    const float* st = g_stacked + (size_t)n * 3 * HH;
    float mpre = (e0 * st[c] + e1 * st[HH + c] + e2 * st[2 * HH + c]) * inv;
    red[t] = mpre; __syncthreads();
    for (int s = 128; s > 0; s >>= 1) { if (t < s) red[t] += red[t + s]; __syncthreads(); }
    if (t == 0) s_mu = red[0] * (1.0f / HH);
    __syncthreads();
    float d = mpre - s_mu;
    red[t] = d * d; __syncthreads();
    for (int s = 128; s > 0; s >>= 1) { if (t < s) red[t] += red[t + s]; __syncthreads(); }
    if (t == 0) s_var = red[0] * (1.0f / HH);
    __syncthreads();
    float meta = d * rsqrtf(s_var + 1e-5f) * gm[c] + bm_[c];
    size_t base = (size_t)n * 2 * HH;
    split2(g_interagg[(size_t)n * HH + c], g_combin_h[base + c],      g_combin_l[base + c]);
    split2(meta,                           g_combin_h[base + HH + c], g_combin_l[base + HH + c]);
}

__global__ void final_kernel(const float* __restrict__ x,
                             const float* __restrict__ g,
                             const float* __restrict__ b,
                             float* __restrict__ out)
{
    int n = blockIdx.x, t = threadIdx.x;
    __shared__ float red[HH];
    __shared__ float s_mu, s_var;
    float v = x[(size_t)n * HH + t] + g_comb[(size_t)n * HH + t];
    red[t] = v; __syncthreads();
    for (int s = 128; s > 0; s >>= 1) { if (t < s) red[t] += red[t + s]; __syncthreads(); }
    if (t == 0) s_mu = red[0] * (1.0f / HH);
    __syncthreads();
    float d = v - s_mu;
    red[t] = d * d; __syncthreads();
    for (int s = 128; s > 0; s >>= 1) { if (t < s) red[t] += red[t + s]; __syncthreads(); }
    if (t == 0) s_var = red[0] * (1.0f / HH);
    __syncthreads();
    out[(size_t)n * HH + t] = d * rsqrtf(s_var + 1e-5f) * g[t] + b[t];
}

// ---------------- host ----------------
static inline void run_gemm(const bf16* Ah, const bf16* Al, int lda, long long sA,
                            const int* ridx, const bf16* A2h, const bf16* A2l,
                            const bf16* Bh, const bf16* Bl, int ldb, long long sB,
                            const float* bias, int sBias,
                            float* C, int ldc, long long sC,
                            bf16* Ch, bf16* Cl, int ldc2, long long sC2,
                            int M, int Nc, int K, int act, int Z)
{
    dim3 grid(Nc / 128, (M + 127) / 128, Z);
    mma_gemm<<<grid, 256, GEMM_SMEM>>>(Ah, Al, lda, sA, ridx, A2h, A2l,
                                       Bh, Bl, ldb, sB, bias, sBias,
                                       C, ldc, sC, Ch, Cl, ldc2, sC2,
                                       M, Nc, K, act);
}
static inline void run_split(const float* src, bf16* hi, bf16* lo, size_t n)
{
    split_kernel<<<(unsigned)((n + 255) / 256), 256>>>(src, hi, lo, (int)n);
}

extern "C" void kernel_launch(void* const* d_in, const int* in_sizes, int n_in,
                              void* d_out, int out_size)
{
    const float* x    = (const float*)d_in[0];
    const int*   ei   = (const int*)d_in[1];
    const float* ea   = (const float*)d_in[2];
    const float* Wq   = (const float*)d_in[3];
    const float* bq   = (const float*)d_in[4];
    const float* Wk   = (const float*)d_in[5];
    const float* bk   = (const float*)d_in[6];
    const float* Wv   = (const float*)d_in[7];
    const float* bv   = (const float*)d_in[8];
    const float* prior= (const float*)d_in[9];
    const float* Wm   = (const float*)d_in[10];
    const float* bm   = (const float*)d_in[11];
    const float* Wir1 = (const float*)d_in[12];
    const float* bir1 = (const float*)d_in[13];
    const float* Wir2 = (const float*)d_in[14];
    const float* bir2 = (const float*)d_in[15];
    const float* Wmp  = (const float*)d_in[16];
    const float* bmp  = (const float*)d_in[17];
    const float* Wa1  = (const float*)d_in[18];
    const float* ba1  = (const float*)d_in[19];
    const float* Wa2  = (const float*)d_in[20];
    const float* gme  = (const float*)d_in[21];
    const float* bme  = (const float*)d_in[22];
    const float* Wc   = (const float*)d_in[23];
    const float* bc   = (const float*)d_in[24];
    const float* gout = (const float*)d_in[25];
    const float* bout = (const float*)d_in[26];
    float* out = (float*)d_out;

    cudaFuncSetAttribute(mma_gemm,
                         cudaFuncAttributeMaxDynamicSharedMemorySize, GEMM_SMEM);

#define SYM(p, s) { void* tmp; cudaGetSymbolAddress(&tmp, s); p = (decltype(p))tmp; }
    float *p_kb, *p_vb, *p_qb, *p_agg, *p_relout, *p_h, *p_stacked, *p_t, *p_comb;
    SYM(p_kb, g_kb); SYM(p_vb, g_vb); SYM(p_qb, g_qb); SYM(p_agg, g_agg);
    SYM(p_relout, g_relout); SYM(p_h, g_h); SYM(p_stacked, g_stacked);
    SYM(p_t, g_t); SYM(p_comb, g_comb);
    bf16 *x_h, *x_l, *ea_h, *ea_l, *agg_h, *agg_l,
         *relout_h, *relout_l, *paths_h, *paths_l, *stacked_h, *stacked_l,
         *combin_h, *combin_l;
    SYM(x_h, g_x_h);   SYM(x_l, g_x_l);
    SYM(ea_h, g_ea_h); SYM(ea_l, g_ea_l);
    SYM(agg_h, g_agg_h);   SYM(agg_l, g_agg_l);
    SYM(relout_h, g_relout_h); SYM(relout_l, g_relout_l);
    SYM(paths_h, g_paths_h);   SYM(paths_l, g_paths_l);
    SYM(stacked_h, g_stacked_h); SYM(stacked_l, g_stacked_l);
    SYM(combin_h, g_combin_h);   SYM(combin_l, g_combin_l);
    bf16 *Wq_h, *Wq_l, *Wk_h, *Wk_l, *Wv_h, *Wv_l, *Wm_h, *Wm_l,
         *Wir1_h, *Wir1_l, *Wmp_h, *Wmp_l, *Wa1_h, *Wa1_l, *Wc_h, *Wc_l;
    SYM(Wq_h, g_Wq_h); SYM(Wq_l, g_Wq_l);
    SYM(Wk_h, g_Wk_h); SYM(Wk_l, g_Wk_l);
    SYM(Wv_h, g_Wv_h); SYM(Wv_l, g_Wv_l);
    SYM(Wm_h, g_Wm_h); SYM(Wm_l, g_Wm_l);
    SYM(Wir1_h, g_Wir1_h); SYM(Wir1_l, g_Wir1_l);
    SYM(Wmp_h, g_Wmp_h);   SYM(Wmp_l, g_Wmp_l);
    SYM(Wa1_h, g_Wa1_h);   SYM(Wa1_l, g_Wa1_l);
    SYM(Wc_h, g_Wc_h);     SYM(Wc_l, g_Wc_l);
#undef SYM

    // one-time splits: x, edge_attr, weights
    run_split(x,    x_h,    x_l,    NN * HH);
    run_split(ea,   ea_h,   ea_l,   RR * EE * FF);
    run_split(Wq,   Wq_h,   Wq_l,   RR * HH * HH);
    run_split(Wk,   Wk_h,   Wk_l,   RR * KVIN * HH);
    run_split(Wv,   Wv_h,   Wv_l,   RR * KVIN * HH);
    run_split(Wm,   Wm_h,   Wm_l,   RR * HH * HH);
    run_split(Wir1, Wir1_h, Wir1_l, RR * HH * HH);
    run_split(Wmp,  Wmp_h,  Wmp_l,  3 * HH * HH);
    run_split(Wa1,  Wa1_h,  Wa1_l,  HH * HH / 2);
    run_split(Wc,   Wc_h,   Wc_l,   2 * HH * HH);

    init0_kernel<<<NN, 256>>>();

    // per-relation pipeline (gather fused into GEMM A-path)
    for (int r = 0; r < RR; r++) {
        const int* ei_r  = ei + (size_t)r * 2 * EE;
        const int* src_r = ei_r;
        const int* dst_r = ei_r + EE;
        const bf16* ea_h_r = ea_h + (size_t)r * EE * FF;
        const bf16* ea_l_r = ea_l + (size_t)r * EE * FF;

        // k = [x[src] | ea] @ Wk + bk   (A gathered via src, tail from ea)
        run_gemm(x_h, x_l, HH, 0, src_r, ea_h_r, ea_l_r,
                 Wk_h + (size_t)r * KVIN * HH, Wk_l + (size_t)r * KVIN * HH,
                 HH, 0, bk + r * HH, 0,
                 p_kb, HH, 0, nullptr, nullptr, 0, 0,
                 EE, HH, KVIN, 0, 1);
        // v = [x[src] | ea] @ Wv + bv
        run_gemm(x_h, x_l, HH, 0, src_r, ea_h_r, ea_l_r,
                 Wv_h + (size_t)r * KVIN * HH, Wv_l + (size_t)r * KVIN * HH,
                 HH, 0, bv + r * HH, 0,
                 p_vb, HH, 0, nullptr, nullptr, 0, 0,
                 EE, HH, KVIN, 0, 1);
        // q = x[dst] @ Wq + bq
        run_gemm(x_h, x_l, HH, 0, dst_r, nullptr, nullptr,
                 Wq_h + (size_t)r * HH * HH, Wq_l + (size_t)r * HH * HH,
                 HH, 0, bq + r * HH, 0,
                 p_qb, HH, 0, nullptr, nullptr, 0, 0,
                 EE, HH, HH, 0, 1);
        // softmax numerator + denominator in one pass (no segment-max)
        score_kernel<<<EE, 256>>>(dst_r, prior + r * NHH);
        scatter_kernel<<<EE, 256>>>(dst_r);
        // split agg to bf16 planes + reset agg/denom for next relation
        split_reset_kernel<<<NN, 256>>>();
        // rel_out[r] = gelu(agg @ Wm + bm) -> column slice r*H of [N, R*H]
        run_gemm(agg_h, agg_l, HH, 0, nullptr, nullptr, nullptr,
                 Wm_h + (size_t)r * HH * HH, Wm_l + (size_t)r * HH * HH,
                 HH, 0, bm + r * HH, 0,
                 p_relout + r * HH, RR * HH, 0,
                 relout_h + r * HH, relout_l + r * HH, RR * HH, 0,
                 NN, HH, HH, 1, 1);
    }

    // h = gelu(all_rel @ W_ir1 + b_ir1)
    run_gemm(relout_h, relout_l, RR * HH, 0, nullptr, nullptr, nullptr,
             Wir1_h, Wir1_l, HH, 0, bir1, 0,
             p_h, HH, 0, nullptr, nullptr, 0, 0,
             NN, HH, RR * HH, 1, 1);
    inter_kernel<<<NN, 256>>>(Wir2, bir2);
    // stacked[p] = paths[p] @ Wmp[p] + bmp[p]
    run_gemm(paths_h, paths_l, 3 * HH, HH, nullptr, nullptr, nullptr,
             Wmp_h, Wmp_l, HH, (long long)HH * HH, bmp, HH,
             p_stacked, 3 * HH, HH,
             stacked_h, stacked_l, 3 * HH, HH,
             NN, HH, HH, 0, 3);
    // t = tanh(stacked @ Wa1 + ba1)
    run_gemm(stacked_h, stacked_l, HH, 0, nullptr, nullptr, nullptr,
             Wa1_h, Wa1_l, HH / 2, 0, ba1, 0,
             p_t, HH / 2, 0, nullptr, nullptr, 0, 0,
             3 * NN, HH / 2, HH, 2, 1);
    meta_kernel<<<NN, 256>>>(Wa2, gme, bme);
    // combined = gelu([inter_agg, meta] @ Wc + bc)
    run_gemm(combin_h, combin_l, 2 * HH, 0, nullptr, nullptr, nullptr,
             Wc_h, Wc_l, HH, 0, bc, 0,
             p_comb, HH, 0, nullptr, nullptr, 0, 0,
             NN, HH, 2 * HH, 1, 1);
    final_kernel<<<NN, 256>>>(x, gout, bout, out);
}

// round 12
// speedup vs baseline: 1.3107x; 1.0225x over previous
#include <cuda_runtime.h>
#include <cuda_bf16.h>
#include <math.h>

#define NN 50000
#define RR 6
#define EE 32768
#define HH 256
#define FF 16
#define NHH 8
#define KVIN (HH + FF)      // 272

typedef __nv_bfloat16 bf16;

// ---------------- fp32 scratch ----------------
__device__ float g_kb[EE * HH];
__device__ float g_vb[EE * HH];
__device__ float g_qb[EE * HH];
__device__ float g_denom[NN * NHH];
__device__ float g_agg[NN * HH];
__device__ float g_h[NN * HH];
__device__ float g_t[NN * 3 * (HH / 2)];
__device__ float g_interagg[NN * HH];
__device__ float g_comb[NN * HH];

// ---------------- bf16 hi/lo planes (activations) ----------------
__device__ bf16 g_x_h[NN * HH],      g_x_l[NN * HH];          // pre-split x
__device__ bf16 g_ea_h[RR * EE * FF], g_ea_l[RR * EE * FF];   // pre-split edge_attr
__device__ bf16 g_agg_h[NN * HH],    g_agg_l[NN * HH];
__device__ bf16 g_relout_h[(size_t)NN * RR * HH],  g_relout_l[(size_t)NN * RR * HH];
__device__ bf16 g_paths_h[NN * 3 * HH],   g_paths_l[NN * 3 * HH];
__device__ bf16 g_stacked_h[NN * 3 * HH], g_stacked_l[NN * 3 * HH];
__device__ bf16 g_combin_h[NN * 2 * HH],  g_combin_l[NN * 2 * HH];

// ---------------- bf16 hi/lo planes (weights) ----------------
__device__ bf16 g_Wq_h[RR * HH * HH],   g_Wq_l[RR * HH * HH];
__device__ bf16 g_Wk_h[RR * KVIN * HH], g_Wk_l[RR * KVIN * HH];
__device__ bf16 g_Wv_h[RR * KVIN * HH], g_Wv_l[RR * KVIN * HH];
__device__ bf16 g_Wm_h[RR * HH * HH],   g_Wm_l[RR * HH * HH];
__device__ bf16 g_Wir1_h[RR * HH * HH], g_Wir1_l[RR * HH * HH];
__device__ bf16 g_Wmp_h[3 * HH * HH],   g_Wmp_l[3 * HH * HH];
__device__ bf16 g_Wa1_h[HH * HH / 2],   g_Wa1_l[HH * HH / 2];
__device__ bf16 g_Wc_h[2 * HH * HH],    g_Wc_l[2 * HH * HH];

__device__ __forceinline__ float gelu_exact(float x) {
    return 0.5f * x * (1.0f + erff(x * 0.70710678118654752f));
}
__device__ __forceinline__ void split2(float v, bf16& hi, bf16& lo) {
    hi = __float2bfloat16(v);
    lo = __float2bfloat16(v - __bfloat162float(hi));
}
__device__ __forceinline__ float b2f(bf16 v) { return __bfloat162float(v); }

// ================= tensor-core GEMM (bf16 split, cp.async 4-stage) ========
// Optional row-gather on A (ridx) + secondary A source for cols >= HH
// (A2, row stride FF, row index = raw row) to feed [x[src] | edge_attr].
// C (fp32) and Chi/Clo (bf16 planes) are each optional.
#define RS_A 24
#define RS_B 136
#define STAGE_BYTES 20992   // Ahi 6144 | Alo 6144 | Bhi 4352 | Blo 4352
#define GEMM_SMEM (4 * STAGE_BYTES)

__device__ __forceinline__ void cp16(unsigned d, const void* s, unsigned sz) {
    asm volatile("cp.async.cg.shared.global [%0], [%1], 16, %2;"
                 :: "r"(d), "l"(s), "r"(sz));
}
__device__ __forceinline__ void ldsm_x4(unsigned& r0, unsigned& r1,
                                        unsigned& r2, unsigned& r3,
                                        unsigned addr) {
    asm volatile("ldmatrix.sync.aligned.m8n8.x4.shared.b16 {%0,%1,%2,%3}, [%4];"
                 : "=r"(r0), "=r"(r1), "=r"(r2), "=r"(r3) : "r"(addr));
}
__device__ __forceinline__ void ldsm_x4t(unsigned& r0, unsigned& r1,
                                         unsigned& r2, unsigned& r3,
                                         unsigned addr) {
    asm volatile("ldmatrix.sync.aligned.m8n8.x4.trans.shared.b16 {%0,%1,%2,%3}, [%4];"
                 : "=r"(r0), "=r"(r1), "=r"(r2), "=r"(r3) : "r"(addr));
}
__device__ __forceinline__ void mma16816(float* c, const unsigned* a,
                                         unsigned b0, unsigned b1) {
    asm volatile(
        "mma.sync.aligned.m16n8k16.row.col.f32.bf16.bf16.f32 "
        "{%0,%1,%2,%3},{%4,%5,%6,%7},{%8,%9},{%0,%1,%2,%3};"
        : "+f"(c[0]), "+f"(c[1]), "+f"(c[2]), "+f"(c[3])
        : "r"(a[0]), "r"(a[1]), "r"(a[2]), "r"(a[3]), "r"(b0), "r"(b1));
}

// NOTE: no min-blocks clause — 128-reg cap forces spills (R4 regression).
__global__ __launch_bounds__(256)
void mma_gemm(const bf16* __restrict__ Ahi, const bf16* __restrict__ Alo,
              int lda, long long sA,
              const int* __restrict__ ridx,
              const bf16* __restrict__ A2hi, const bf16* __restrict__ A2lo,
              const bf16* __restrict__ Bhi, const bf16* __restrict__ Blo,
              int ldb, long long sB,
              const float* __restrict__ bias, int sBias,
              float* __restrict__ C, int ldc, long long sC,
              bf16* __restrict__ Chi, bf16* __restrict__ Clo,
              int ldc2, long long sC2,
              int M, int Nc, int K, int act)
{
    extern __shared__ __align__(128) char smem[];
    const unsigned smemBase = (unsigned)__cvta_generic_to_shared(smem);

    const int z = blockIdx.z;
    Ahi += (size_t)z * sA;  Alo += (size_t)z * sA;
    Bhi += (size_t)z * sB;  Blo += (size_t)z * sB;
    bias += (size_t)z * sBias;
    if (C)   C += (size_t)z * sC;
    if (Chi) { Chi += (size_t)z * sC2; Clo += (size_t)z * sC2; }

    const int tid = threadIdx.x;
    const int lane = tid & 31;
    const int w = tid >> 5;
    const int wm = w & 3;
    const int wn = w >> 2;
    const int rowBase = blockIdx.y * 128;
    const int colBase = blockIdx.x * 128;
    const int nChunks = K >> 4;

    float acc[2][8][4];
#pragma unroll
    for (int i = 0; i < 2; i++)
#pragma unroll
        for (int j = 0; j < 8; j++)
#pragma unroll
            for (int q = 0; q < 4; q++) acc[i][j][q] = 0.0f;

    unsigned offA[2], offB[4];
#pragma unroll
    for (int mt = 0; mt < 2; mt++)
        offA[mt] = (wm * 32 + mt * 16 + (lane & 15)) * RS_A + (lane >> 4) * 8;
#pragma unroll
    for (int g = 0; g < 4; g++)
        offB[g] = (lane & 15) * RS_B + wn * 64 + g * 16 + (lane >> 4) * 8;

    const int aRow = tid >> 1;
    const int aCh  = (tid & 1) << 3;
    const int bRow = tid >> 4;
    const int bCh  = (tid & 15) << 3;
    const int rIdx = rowBase + aRow;
    const bool rOK = rIdx < M;
    const int gRow = rOK ? (ridx ? ridx[rIdx] : rIdx) : 0;
    const bf16* aRowH = Ahi + (size_t)gRow * lda;
    const bf16* aRowL = Alo + (size_t)gRow * lda;
    const bf16* a2H = A2hi ? A2hi + (size_t)rIdx * FF : nullptr;
    const bf16* a2L = A2hi ? A2lo + (size_t)rIdx * FF : nullptr;
    const unsigned aSz = rOK ? 16u : 0u;

    auto issue_stage = [&](int c) {
        if (c < nChunks) {
            const int k0 = c << 4;
            const unsigned sb = smemBase + (c & 3) * STAGE_BYTES;
            unsigned da = sb + (aRow * RS_A + aCh) * 2;
            if (a2H == nullptr || k0 < HH) {
                cp16(da,        aRowH + k0 + aCh, aSz);
                cp16(da + 6144, aRowL + k0 + aCh, aSz);
            } else {
                cp16(da,        a2H + (k0 - HH) + aCh, aSz);
                cp16(da + 6144, a2L + (k0 - HH) + aCh, aSz);
            }
            size_t bo = (size_t)(k0 + bRow) * ldb + colBase + bCh;
            unsigned db = sb + 12288 + (bRow * RS_B + bCh) * 2;
            cp16(db,        Bhi + bo, 16u);
            cp16(db + 4352, Blo + bo, 16u);
        }
        asm volatile("cp.async.commit_group;" ::);
    };

    issue_stage(0); issue_stage(1); issue_stage(2);

    for (int k = 0; k < nChunks; k++) {
        asm volatile("cp.async.wait_group 2;" ::);
        __syncthreads();
        issue_stage(k + 3);

        const unsigned sb = smemBase + (k & 3) * STAGE_BYTES;
        unsigned ah[2][4], al[2][4];
#pragma unroll
        for (int mt = 0; mt < 2; mt++) {
            ldsm_x4(ah[mt][0], ah[mt][1], ah[mt][2], ah[mt][3], sb + offA[mt] * 2);
            ldsm_x4(al[mt][0], al[mt][1], al[mt][2], al[mt][3], sb + 6144 + offA[mt] * 2);
        }
#pragma unroll
        for (int g = 0; g < 4; g++) {
            unsigned bh[4], bl[4];
            ldsm_x4t(bh[0], bh[1], bh[2], bh[3], sb + 12288 + offB[g] * 2);
            ldsm_x4t(bl[0], bl[1], bl[2], bl[3], sb + 16640 + offB[g] * 2);
#pragma unroll
            for (int mt = 0; mt < 2; mt++) {
                float* a0 = acc[mt][g * 2];
                float* a1 = acc[mt][g * 2 + 1];
                mma16816(a0, ah[mt], bh[0], bh[1]);
                mma16816(a0, ah[mt], bl[0], bl[1]);
                mma16816(a0, al[mt], bh[0], bh[1]);
                mma16816(a1, ah[mt], bh[2], bh[3]);
                mma16816(a1, ah[mt], bl[2], bl[3]);
                mma16816(a1, al[mt], bh[2], bh[3]);
            }
        }
    }

#pragma unroll
    for (int mt = 0; mt < 2; mt++) {
        int r0 = rowBase + wm * 32 + mt * 16 + (lane >> 2);
#pragma unroll
        for (int half = 0; half < 2; half++) {
            int r = r0 + half * 8;
            if (r >= M) continue;
#pragma unroll
            for (int nt = 0; nt < 8; nt++) {
                int cg = colBase + wn * 64 + nt * 8 + (lane & 3) * 2;
                float v0 = acc[mt][nt][half * 2]     + bias[cg];
                float v1 = acc[mt][nt][half * 2 + 1] + bias[cg + 1];
                if (act == 1) { v0 = gelu_exact(v0); v1 = gelu_exact(v1); }
                else if (act == 2) { v0 = tanhf(v0); v1 = tanhf(v1); }
                if (C)
                    *(float2*)&C[(size_t)r * ldc + cg] = make_float2(v0, v1);
                if (Chi) {
                    bf16 h0, l0, h1, l1;
                    split2(v0, h0, l0); split2(v1, h1, l1);
                    __nv_bfloat162 ph; ph.x = h0; ph.y = h1;
                    __nv_bfloat162 pl; pl.x = l0; pl.y = l1;
                    *(__nv_bfloat162*)&Chi[(size_t)r * ldc2 + cg] = ph;
                    *(__nv_bfloat162*)&Clo[(size_t)r * ldc2 + cg] = pl;
                }
            }
        }
    }
}

// ---------------- elementwise helpers ----------------
__global__ void split_kernel(const float* __restrict__ src,
                             bf16* __restrict__ hi, bf16* __restrict__ lo, int n)
{
    int i = blockIdx.x * 256 + threadIdx.x;
    if (i < n) split2(src[i], hi[i], lo[i]);
}

// ---------------- per-relation kernels ----------------
// zero agg + denom (once, before loop)
__global__ void init0_kernel()
{
    int n = blockIdx.x, t = threadIdx.x;
    g_agg[(size_t)n * HH + t] = 0.0f;
    if (t < NHH) g_denom[n * NHH + t] = 0.0f;
}

// fused attention: score -> exp -> accumulate denom AND unnormalized ex*v.
// Normalization by denom happens later in split_reset (denom const per dst).
__global__ void attn_kernel(const int* __restrict__ dst_r,
                            const float* __restrict__ prior_r)
{
    int e = blockIdx.x, t = threadIdx.x;
    int h = t >> 5, lane = t & 31;
    float p = g_qb[e * HH + t] * g_kb[e * HH + t];
#pragma unroll
    for (int o = 16; o > 0; o >>= 1) p += __shfl_down_sync(0xFFFFFFFFu, p, o);
    float ex;
    if (lane == 0) ex = expf(p * 0.17677669529663689f * prior_r[h]);
    ex = __shfl_sync(0xFFFFFFFFu, ex, 0);
    int dst = dst_r[e];
    if (lane == 0) atomicAdd(&g_denom[dst * NHH + h], ex);
    atomicAdd(&g_agg[(size_t)dst * HH + t], ex * g_vb[e * HH + t]);
}

// normalize agg by denom, split to bf16 planes, re-zero agg/denom
__global__ void split_reset_kernel()
{
    int n = blockIdx.x, t = threadIdx.x;
    size_t idx = (size_t)n * HH + t;
    float den = g_denom[n * NHH + (t >> 5)] + 1e-16f;
    float v = g_agg[idx] / den;
    split2(v, g_agg_h[idx], g_agg_l[idx]);
    g_agg[idx] = 0.0f;
    __syncthreads();
    if (t < NHH) g_denom[n * NHH + t] = 0.0f;
}

// ---------------- inter-relation fusion (reads bf16 relout planes) --------
__global__ void inter_kernel(const float* __restrict__ Wir2,
                             const float* __restrict__ bir2)
{
    int n = blockIdx.x, t = threadIdx.x;
    int w = t >> 5, lane = t & 31;
    __shared__ float logit[RR];
    if (w < RR) {
        float s = 0.0f;
        for (int i = lane; i < HH; i += 32)
            s += g_h[(size_t)n * HH + i] * Wir2[i * RR + w];
#pragma unroll
        for (int o = 16; o > 0; o >>= 1) s += __shfl_down_sync(0xFFFFFFFFu, s, o);
        if (lane == 0) logit[w] = s + bir2[w];
    }
    __syncthreads();
    float l[RR]; float mx = -1e30f;
#pragma unroll
    for (int r = 0; r < RR; r++) { l[r] = logit[r]; mx = fmaxf(mx, l[r]); }
    float sum = 0.0f;
#pragma unroll
    for (int r = 0; r < RR; r++) { l[r] = expf(l[r] - mx); sum += l[r]; }
    float inv = 1.0f / sum;
    int c = t;
    const bf16* roh = g_relout_h + (size_t)n * (RR * HH);
    const bf16* rol = g_relout_l + (size_t)n * (RR * HH);
    float rv[RR];
    float acc = 0.0f;
#pragma unroll
    for (int r = 0; r < RR; r++) {
        rv[r] = b2f(roh[r * HH + c]) + b2f(rol[r * HH + c]);
        acc += l[r] * inv * rv[r];
    }
    g_interagg[(size_t)n * HH + c] = acc;
    size_t base = (size_t)n * 3 * HH;
    split2(rv[2] + rv[3], g_paths_h[base + c],          g_paths_l[base + c]);
    split2(rv[4] + rv[0], g_paths_h[base + HH + c],     g_paths_l[base + HH + c]);
    split2(rv[1] + rv[5], g_paths_h[base + 2 * HH + c], g_paths_l[base + 2 * HH + c]);
}

__global__ void meta_kernel(const float* __restrict__ Wa2,
                            const float* __restrict__ gm,
                            const float* __restrict__ bm_)
{
    int n = blockIdx.x, t = threadIdx.x;
    int w = t >> 5, lane = t & 31;
    __shared__ float sl[3];
    __shared__ float red[HH];
    __shared__ float s_mu, s_var;
    if (w < 3) {
        float s = 0.0f;
        for (int i = lane; i < HH / 2; i += 32)
            s += g_t[((size_t)n * 3 + w) * (HH / 2) + i] * Wa2[i];
#pragma unroll
        for (int o = 16; o > 0; o >>= 1) s += __shfl_down_sync(0xFFFFFFFFu, s, o);
        if (lane == 0) sl[w] = s;
    }
    __syncthreads();
    float a0 = sl[0], a1 = sl[1], a2 = sl[2];
    float mx = fmaxf(a0, fmaxf(a1, a2));
    float e0 = expf(a0 - mx), e1 = expf(a1 - mx), e2 = expf(a2 - mx);
    float inv = 1.0f / (e0 + e1 + e2);
    int c = t;
    const bf16* sth = g_stacked_h + (size_t)n * 3 * HH;
    const bf16* stl = g_stacked_l + (size_t)n * 3 * HH;
    float s0 = b2f(sth[c])          + b2f(stl[c]);
    float s1 = b2f(sth[HH + c])     + b2f(stl[HH + c]);
    float s2 = b2f(sth[2 * HH + c]) + b2f(stl[2 * HH + c]);
    float mpre = (e0 * s0 + e1 * s1 + e2 * s2) * inv;
    red[t] = mpre; __syncthreads();
    for (int s = 128; s > 0; s >>= 1) { if (t < s) red[t] += red[t + s]; __syncthreads(); }
    if (t == 0) s_mu = red[0] * (1.0f / HH);
    __syncthreads();
    float d = mpre - s_mu;
    red[t] = d * d; __syncthreads();
    for (int s = 128; s > 0; s >>= 1) { if (t < s) red[t] += red[t + s]; __syncthreads(); }
    if (t == 0) s_var = red[0] * (1.0f / HH);
    __syncthreads();
    float meta = d * rsqrtf(s_var + 1e-5f) * gm[c] + bm_[c];
    size_t base = (size_t)n * 2 * HH;
    split2(g_interagg[(size_t)n * HH + c], g_combin_h[base + c],      g_combin_l[base + c]);
    split2(meta,                           g_combin_h[base + HH + c], g_combin_l[base + HH + c]);
}

__global__ void final_kernel(const float* __restrict__ x,
                             const float* __restrict__ g,
                             const float* __restrict__ b,
                             float* __restrict__ out)
{
    int n = blockIdx.x, t = threadIdx.x;
    __shared__ float red[HH];
    __shared__ float s_mu, s_var;
    float v = x[(size_t)n * HH + t] + g_comb[(size_t)n * HH + t];
    red[t] = v; __syncthreads();
    for (int s = 128; s > 0; s >>= 1) { if (t < s) red[t] += red[t + s]; __syncthreads(); }
    if (t == 0) s_mu = red[0] * (1.0f / HH);
    __syncthreads();
    float d = v - s_mu;
    red[t] = d * d; __syncthreads();
    for (int s = 128; s > 0; s >>= 1) { if (t < s) red[t] += red[t + s]; __syncthreads(); }
    if (t == 0) s_var = red[0] * (1.0f / HH);
    __syncthreads();
    out[(size_t)n * HH + t] = d * rsqrtf(s_var + 1e-5f) * g[t] + b[t];
}

// ---------------- host ----------------
static inline void run_gemm(const bf16* Ah, const bf16* Al, int lda, long long sA,
                            const int* ridx, const bf16* A2h, const bf16* A2l,
                            const bf16* Bh, const bf16* Bl, int ldb, long long sB,
                            const float* bias, int sBias,
                            float* C, int ldc, long long sC,
                            bf16* Ch, bf16* Cl, int ldc2, long long sC2,
                            int M, int Nc, int K, int act, int Z)
{
    dim3 grid(Nc / 128, (M + 127) / 128, Z);
    mma_gemm<<<grid, 256, GEMM_SMEM>>>(Ah, Al, lda, sA, ridx, A2h, A2l,
                                       Bh, Bl, ldb, sB, bias, sBias,
                                       C, ldc, sC, Ch, Cl, ldc2, sC2,
                                       M, Nc, K, act);
}
static inline void run_split(const float* src, bf16* hi, bf16* lo, size_t n)
{
    split_kernel<<<(unsigned)((n + 255) / 256), 256>>>(src, hi, lo, (int)n);
}

extern "C" void kernel_launch(void* const* d_in, const int* in_sizes, int n_in,
                              void* d_out, int out_size)
{
    const float* x    = (const float*)d_in[0];
    const int*   ei   = (const int*)d_in[1];
    const float* ea   = (const float*)d_in[2];
    const float* Wq   = (const float*)d_in[3];
    const float* bq   = (const float*)d_in[4];
    const float* Wk   = (const float*)d_in[5];
    const float* bk   = (const float*)d_in[6];
    const float* Wv   = (const float*)d_in[7];
    const float* bv   = (const float*)d_in[8];
    const float* prior= (const float*)d_in[9];
    const float* Wm   = (const float*)d_in[10];
    const float* bm   = (const float*)d_in[11];
    const float* Wir1 = (const float*)d_in[12];
    const float* bir1 = (const float*)d_in[13];
    const float* Wir2 = (const float*)d_in[14];
    const float* bir2 = (const float*)d_in[15];
    const float* Wmp  = (const float*)d_in[16];
    const float* bmp  = (const float*)d_in[17];
    const float* Wa1  = (const float*)d_in[18];
    const float* ba1  = (const float*)d_in[19];
    const float* Wa2  = (const float*)d_in[20];
    const float* gme  = (const float*)d_in[21];
    const float* bme  = (const float*)d_in[22];
    const float* Wc   = (const float*)d_in[23];
    const float* bc   = (const float*)d_in[24];
    const float* gout = (const float*)d_in[25];
    const float* bout = (const float*)d_in[26];
    float* out = (float*)d_out;

    cudaFuncSetAttribute(mma_gemm,
                         cudaFuncAttributeMaxDynamicSharedMemorySize, GEMM_SMEM);

#define SYM(p, s) { void* tmp; cudaGetSymbolAddress(&tmp, s); p = (decltype(p))tmp; }
    float *p_kb, *p_vb, *p_qb, *p_h, *p_t, *p_comb;
    SYM(p_kb, g_kb); SYM(p_vb, g_vb); SYM(p_qb, g_qb);
    SYM(p_h, g_h); SYM(p_t, g_t); SYM(p_comb, g_comb);
    bf16 *x_h, *x_l, *ea_h, *ea_l, *agg_h, *agg_l,
         *relout_h, *relout_l, *paths_h, *paths_l, *stacked_h, *stacked_l,
         *combin_h, *combin_l;
    SYM(x_h, g_x_h);   SYM(x_l, g_x_l);
    SYM(ea_h, g_ea_h); SYM(ea_l, g_ea_l);
    SYM(agg_h, g_agg_h);   SYM(agg_l, g_agg_l);
    SYM(relout_h, g_relout_h); SYM(relout_l, g_relout_l);
    SYM(paths_h, g_paths_h);   SYM(paths_l, g_paths_l);
    SYM(stacked_h, g_stacked_h); SYM(stacked_l, g_stacked_l);
    SYM(combin_h, g_combin_h);   SYM(combin_l, g_combin_l);
    bf16 *Wq_h, *Wq_l, *Wk_h, *Wk_l, *Wv_h, *Wv_l, *Wm_h, *Wm_l,
         *Wir1_h, *Wir1_l, *Wmp_h, *Wmp_l, *Wa1_h, *Wa1_l, *Wc_h, *Wc_l;
    SYM(Wq_h, g_Wq_h); SYM(Wq_l, g_Wq_l);
    SYM(Wk_h, g_Wk_h); SYM(Wk_l, g_Wk_l);
    SYM(Wv_h, g_Wv_h); SYM(Wv_l, g_Wv_l);
    SYM(Wm_h, g_Wm_h); SYM(Wm_l, g_Wm_l);
    SYM(Wir1_h, g_Wir1_h); SYM(Wir1_l, g_Wir1_l);
    SYM(Wmp_h, g_Wmp_h);   SYM(Wmp_l, g_Wmp_l);
    SYM(Wa1_h, g_Wa1_h);   SYM(Wa1_l, g_Wa1_l);
    SYM(Wc_h, g_Wc_h);     SYM(Wc_l, g_Wc_l);
#undef SYM

    // one-time splits: x, edge_attr, weights
    run_split(x,    x_h,    x_l,    NN * HH);
    run_split(ea,   ea_h,   ea_l,   RR * EE * FF);
    run_split(Wq,   Wq_h,   Wq_l,   RR * HH * HH);
    run_split(Wk,   Wk_h,   Wk_l,   RR * KVIN * HH);
    run_split(Wv,   Wv_h,   Wv_l,   RR * KVIN * HH);
    run_split(Wm,   Wm_h,   Wm_l,   RR * HH * HH);
    run_split(Wir1, Wir1_h, Wir1_l, RR * HH * HH);
    run_split(Wmp,  Wmp_h,  Wmp_l,  3 * HH * HH);
    run_split(Wa1,  Wa1_h,  Wa1_l,  HH * HH / 2);
    run_split(Wc,   Wc_h,   Wc_l,   2 * HH * HH);

    init0_kernel<<<NN, 256>>>();

    // per-relation pipeline (gather fused into GEMM A-path)
    for (int r = 0; r < RR; r++) {
        const int* ei_r  = ei + (size_t)r * 2 * EE;
        const int* src_r = ei_r;
        const int* dst_r = ei_r + EE;
        const bf16* ea_h_r = ea_h + (size_t)r * EE * FF;
        const bf16* ea_l_r = ea_l + (size_t)r * EE * FF;

        // k = [x[src] | ea] @ Wk + bk   (A gathered via src, tail from ea)
        run_gemm(x_h, x_l, HH, 0, src_r, ea_h_r, ea_l_r,
                 Wk_h + (size_t)r * KVIN * HH, Wk_l + (size_t)r * KVIN * HH,
                 HH, 0, bk + r * HH, 0,
                 p_kb, HH, 0, nullptr, nullptr, 0, 0,
                 EE, HH, KVIN, 0, 1);
        // v = [x[src] | ea] @ Wv + bv
        run_gemm(x_h, x_l, HH, 0, src_r, ea_h_r, ea_l_r,
                 Wv_h + (size_t)r * KVIN * HH, Wv_l + (size_t)r * KVIN * HH,
                 HH, 0, bv + r * HH, 0,
                 p_vb, HH, 0, nullptr, nullptr, 0, 0,
                 EE, HH, KVIN, 0, 1);
        // q = x[dst] @ Wq + bq
        run_gemm(x_h, x_l, HH, 0, dst_r, nullptr, nullptr,
                 Wq_h + (size_t)r * HH * HH, Wq_l + (size_t)r * HH * HH,
                 HH, 0, bq + r * HH, 0,
                 p_qb, HH, 0, nullptr, nullptr, 0, 0,
                 EE, HH, HH, 0, 1);
        // fused attention: exp(score) -> denom + unnormalized ex*v
        attn_kernel<<<EE, 256>>>(dst_r, prior + r * NHH);
        // normalize + split agg, reset agg/denom
        split_reset_kernel<<<NN, 256>>>();
        // rel_out[r] = gelu(agg @ Wm + bm) -> bf16 planes only, col slice r*H
        run_gemm(agg_h, agg_l, HH, 0, nullptr, nullptr, nullptr,
                 Wm_h + (size_t)r * HH * HH, Wm_l + (size_t)r * HH * HH,
                 HH, 0, bm + r * HH, 0,
                 nullptr, 0, 0,
                 relout_h + r * HH, relout_l + r * HH, RR * HH, 0,
                 NN, HH, HH, 1, 1);
    }

    // h = gelu(all_rel @ W_ir1 + b_ir1)
    run_gemm(relout_h, relout_l, RR * HH, 0, nullptr, nullptr, nullptr,
             Wir1_h, Wir1_l, HH, 0, bir1, 0,
             p_h, HH, 0, nullptr, nullptr, 0, 0,
             NN, HH, RR * HH, 1, 1);
    inter_kernel<<<NN, 256>>>(Wir2, bir2);
    // stacked[p] = paths[p] @ Wmp[p] + bmp[p] -> bf16 planes only
    run_gemm(paths_h, paths_l, 3 * HH, HH, nullptr, nullptr, nullptr,
             Wmp_h, Wmp_l, HH, (long long)HH * HH, bmp, HH,
             nullptr, 0, 0,
             stacked_h, stacked_l, 3 * HH, HH,
             NN, HH, HH, 0, 3);
    // t = tanh(stacked @ Wa1 + ba1)
    run_gemm(stacked_h, stacked_l, HH, 0, nullptr, nullptr, nullptr,
             Wa1_h, Wa1_l, HH / 2, 0, ba1, 0,
             p_t, HH / 2, 0, nullptr, nullptr, 0, 0,
             3 * NN, HH / 2, HH, 2, 1);
    meta_kernel<<<NN, 256>>>(Wa2, gme, bme);
    // combined = gelu([inter_agg, meta] @ Wc + bc)
    run_gemm(combin_h, combin_l, 2 * HH, 0, nullptr, nullptr, nullptr,
             Wc_h, Wc_l, HH, 0, bc, 0,
             p_comb, HH, 0, nullptr, nullptr, 0, 0,
             NN, HH, 2 * HH, 1, 1);
    final_kernel<<<NN, 256>>>(x, gout, bout, out);
}

// round 14
// speedup vs baseline: 1.3483x; 1.0286x over previous
#include <cuda_runtime.h>
#include <cuda_bf16.h>
#include <math.h>

#define NN 50000
#define RR 6
#define EE 32768
#define HH 256
#define FF 16
#define NHH 8
#define KVIN (HH + FF)      // 272

typedef __nv_bfloat16 bf16;

// ---------------- fp32 scratch ----------------
__device__ float g_kvb[EE * 512];        // [e][ k(256) | v(256) ]
__device__ float g_qb[EE * HH];
__device__ float g_denom[NN * NHH];
__device__ float g_agg[NN * HH];
__device__ float g_h[NN * HH];
__device__ float g_t[NN * 3 * (HH / 2)];
__device__ float g_interagg[NN * HH];
__device__ float g_comb[NN * HH];

// ---------------- bf16 hi/lo planes (activations) ----------------
__device__ bf16 g_x_h[NN * HH],      g_x_l[NN * HH];          // pre-split x
__device__ bf16 g_ea_h[RR * EE * FF], g_ea_l[RR * EE * FF];   // pre-split edge_attr
__device__ bf16 g_agg_h[NN * HH],    g_agg_l[NN * HH];
__device__ bf16 g_relout_h[(size_t)NN * RR * HH],  g_relout_l[(size_t)NN * RR * HH];
__device__ bf16 g_paths_h[NN * 3 * HH],   g_paths_l[NN * 3 * HH];
__device__ bf16 g_stacked_h[NN * 3 * HH], g_stacked_l[NN * 3 * HH];
__device__ bf16 g_combin_h[NN * 2 * HH],  g_combin_l[NN * 2 * HH];

// ---------------- bf16 hi/lo planes (weights) ----------------
__device__ bf16 g_Wq_h[RR * HH * HH],   g_Wq_l[RR * HH * HH];
__device__ bf16 g_Wkv_h[RR * KVIN * 512], g_Wkv_l[RR * KVIN * 512];  // [Wk|Wv]
__device__ float g_bkv[RR * 512];
__device__ bf16 g_Wm_h[RR * HH * HH],   g_Wm_l[RR * HH * HH];
__device__ bf16 g_Wir1_h[RR * HH * HH], g_Wir1_l[RR * HH * HH];
__device__ bf16 g_Wmp_h[3 * HH * HH],   g_Wmp_l[3 * HH * HH];
__device__ bf16 g_Wa1_h[HH * HH / 2],   g_Wa1_l[HH * HH / 2];
__device__ bf16 g_Wc_h[2 * HH * HH],    g_Wc_l[2 * HH * HH];

__device__ __forceinline__ float gelu_exact(float x) {
    return 0.5f * x * (1.0f + erff(x * 0.70710678118654752f));
}
__device__ __forceinline__ void split2(float v, bf16& hi, bf16& lo) {
    hi = __float2bfloat16(v);
    lo = __float2bfloat16(v - __bfloat162float(hi));
}
__device__ __forceinline__ float b2f(bf16 v) { return __bfloat162float(v); }

// ================= tensor-core GEMM (bf16 split, cp.async 4-stage) ========
#define RS_A 24
#define RS_B 136
#define STAGE_BYTES 20992   // Ahi 6144 | Alo 6144 | Bhi 4352 | Blo 4352
#define GEMM_SMEM (4 * STAGE_BYTES)

__device__ __forceinline__ void cp16(unsigned d, const void* s, unsigned sz) {
    asm volatile("cp.async.cg.shared.global [%0], [%1], 16, %2;"
                 :: "r"(d), "l"(s), "r"(sz));
}
__device__ __forceinline__ void ldsm_x4(unsigned& r0, unsigned& r1,
                                        unsigned& r2, unsigned& r3,
                                        unsigned addr) {
    asm volatile("ldmatrix.sync.aligned.m8n8.x4.shared.b16 {%0,%1,%2,%3}, [%4];"
                 : "=r"(r0), "=r"(r1), "=r"(r2), "=r"(r3) : "r"(addr));
}
__device__ __forceinline__ void ldsm_x4t(unsigned& r0, unsigned& r1,
                                         unsigned& r2, unsigned& r3,
                                         unsigned addr) {
    asm volatile("ldmatrix.sync.aligned.m8n8.x4.trans.shared.b16 {%0,%1,%2,%3}, [%4];"
                 : "=r"(r0), "=r"(r1), "=r"(r2), "=r"(r3) : "r"(addr));
}
__device__ __forceinline__ void mma16816(float* c, const unsigned* a,
                                         unsigned b0, unsigned b1) {
    asm volatile(
        "mma.sync.aligned.m16n8k16.row.col.f32.bf16.bf16.f32 "
        "{%0,%1,%2,%3},{%4,%5,%6,%7},{%8,%9},{%0,%1,%2,%3};"
        : "+f"(c[0]), "+f"(c[1]), "+f"(c[2]), "+f"(c[3])
        : "r"(a[0]), "r"(a[1]), "r"(a[2]), "r"(a[3]), "r"(b0), "r"(b1));
}

// NOTE: no min-blocks clause — 128-reg cap forces spills (R4 regression).
__global__ __launch_bounds__(256)
void mma_gemm(const bf16* __restrict__ Ahi, const bf16* __restrict__ Alo,
              int lda, long long sA,
              const int* __restrict__ ridx,
              const bf16* __restrict__ A2hi, const bf16* __restrict__ A2lo,
              const bf16* __restrict__ Bhi, const bf16* __restrict__ Blo,
              int ldb, long long sB,
              const float* __restrict__ bias, int sBias,
              float* __restrict__ C, int ldc, long long sC,
              bf16* __restrict__ Chi, bf16* __restrict__ Clo,
              int ldc2, long long sC2,
              int M, int Nc, int K, int act)
{
    extern __shared__ __align__(128) char smem[];
    const unsigned smemBase = (unsigned)__cvta_generic_to_shared(smem);

    const int z = blockIdx.z;
    Ahi += (size_t)z * sA;  Alo += (size_t)z * sA;
    Bhi += (size_t)z * sB;  Blo += (size_t)z * sB;
    bias += (size_t)z * sBias;
    if (C)   C += (size_t)z * sC;
    if (Chi) { Chi += (size_t)z * sC2; Clo += (size_t)z * sC2; }

    const int tid = threadIdx.x;
    const int lane = tid & 31;
    const int w = tid >> 5;
    const int wm = w & 3;
    const int wn = w >> 2;
    const int rowBase = blockIdx.y * 128;
    const int colBase = blockIdx.x * 128;
    const int nChunks = K >> 4;

    float acc[2][8][4];
#pragma unroll
    for (int i = 0; i < 2; i++)
#pragma unroll
        for (int j = 0; j < 8; j++)
#pragma unroll
            for (int q = 0; q < 4; q++) acc[i][j][q] = 0.0f;

    unsigned offA[2], offB[4];
#pragma unroll
    for (int mt = 0; mt < 2; mt++)
        offA[mt] = (wm * 32 + mt * 16 + (lane & 15)) * RS_A + (lane >> 4) * 8;
#pragma unroll
    for (int g = 0; g < 4; g++)
        offB[g] = (lane & 15) * RS_B + wn * 64 + g * 16 + (lane >> 4) * 8;

    const int aRow = tid >> 1;
    const int aCh  = (tid & 1) << 3;
    const int bRow = tid >> 4;
    const int bCh  = (tid & 15) << 3;
    const int rIdx = rowBase + aRow;
    const bool rOK = rIdx < M;
    const int gRow = rOK ? (ridx ? ridx[rIdx] : rIdx) : 0;
    const bf16* aRowH = Ahi + (size_t)gRow * lda;
    const bf16* aRowL = Alo + (size_t)gRow * lda;
    const bf16* a2H = A2hi ? A2hi + (size_t)rIdx * FF : nullptr;
    const bf16* a2L = A2hi ? A2lo + (size_t)rIdx * FF : nullptr;
    const unsigned aSz = rOK ? 16u : 0u;

    auto issue_stage = [&](int c) {
        if (c < nChunks) {
            const int k0 = c << 4;
            const unsigned sb = smemBase + (c & 3) * STAGE_BYTES;
            unsigned da = sb + (aRow * RS_A + aCh) * 2;
            if (a2H == nullptr || k0 < HH) {
                cp16(da,        aRowH + k0 + aCh, aSz);
                cp16(da + 6144, aRowL + k0 + aCh, aSz);
            } else {
                cp16(da,        a2H + (k0 - HH) + aCh, aSz);
                cp16(da + 6144, a2L + (k0 - HH) + aCh, aSz);
            }
            size_t bo = (size_t)(k0 + bRow) * ldb + colBase + bCh;
            unsigned db = sb + 12288 + (bRow * RS_B + bCh) * 2;
            cp16(db,        Bhi + bo, 16u);
            cp16(db + 4352, Blo + bo, 16u);
        }
        asm volatile("cp.async.commit_group;" ::);
    };

    issue_stage(0); issue_stage(1); issue_stage(2);

    for (int k = 0; k < nChunks; k++) {
        asm volatile("cp.async.wait_group 2;" ::);
        __syncthreads();
        issue_stage(k + 3);

        const unsigned sb = smemBase + (k & 3) * STAGE_BYTES;
        unsigned ah[2][4], al[2][4];
#pragma unroll
        for (int mt = 0; mt < 2; mt++) {
            ldsm_x4(ah[mt][0], ah[mt][1], ah[mt][2], ah[mt][3], sb + offA[mt] * 2);
            ldsm_x4(al[mt][0], al[mt][1], al[mt][2], al[mt][3], sb + 6144 + offA[mt] * 2);
        }
#pragma unroll
        for (int g = 0; g < 4; g++) {
            unsigned bh[4], bl[4];
            ldsm_x4t(bh[0], bh[1], bh[2], bh[3], sb + 12288 + offB[g] * 2);
            ldsm_x4t(bl[0], bl[1], bl[2], bl[3], sb + 16640 + offB[g] * 2);
#pragma unroll
            for (int mt = 0; mt < 2; mt++) {
                float* a0 = acc[mt][g * 2];
                float* a1 = acc[mt][g * 2 + 1];
                mma16816(a0, ah[mt], bh[0], bh[1]);
                mma16816(a0, ah[mt], bl[0], bl[1]);
                mma16816(a0, al[mt], bh[0], bh[1]);
                mma16816(a1, ah[mt], bh[2], bh[3]);
                mma16816(a1, ah[mt], bl[2], bl[3]);
                mma16816(a1, al[mt], bh[2], bh[3]);
            }
        }
    }

#pragma unroll
    for (int mt = 0; mt < 2; mt++) {
        int r0 = rowBase + wm * 32 + mt * 16 + (lane >> 2);
#pragma unroll
        for (int half = 0; half < 2; half++) {
            int r = r0 + half * 8;
            if (r >= M) continue;
#pragma unroll
            for (int nt = 0; nt < 8; nt++) {
                int cg = colBase + wn * 64 + nt * 8 + (lane & 3) * 2;
                float v0 = acc[mt][nt][half * 2]     + bias[cg];
                float v1 = acc[mt][nt][half * 2 + 1] + bias[cg + 1];
                if (act == 1) { v0 = gelu_exact(v0); v1 = gelu_exact(v1); }
                else if (act == 2) { v0 = tanhf(v0); v1 = tanhf(v1); }
                if (C)
                    *(float2*)&C[(size_t)r * ldc + cg] = make_float2(v0, v1);
                if (Chi) {
                    bf16 h0, l0, h1, l1;
                    split2(v0, h0, l0); split2(v1, h1, l1);
                    __nv_bfloat162 ph; ph.x = h0; ph.y = h1;
                    __nv_bfloat162 pl; pl.x = l0; pl.y = l1;
                    *(__nv_bfloat162*)&Chi[(size_t)r * ldc2 + cg] = ph;
                    *(__nv_bfloat162*)&Clo[(size_t)r * ldc2 + cg] = pl;
                }
            }
        }
    }
}

// ---------------- elementwise helpers ----------------
__global__ void split_kernel(const float* __restrict__ src,
                             bf16* __restrict__ hi, bf16* __restrict__ lo, int n)
{
    int i = blockIdx.x * 256 + threadIdx.x;
    if (i < n) split2(src[i], hi[i], lo[i]);
}

// pack [Wk|Wv] -> Wkv hi/lo planes (RR x KVIN x 512)
__global__ void pack_kv_kernel(const float* __restrict__ Wk,
                               const float* __restrict__ Wv)
{
    int i = blockIdx.x * 256 + threadIdx.x;
    if (i >= RR * KVIN * 512) return;
    int col = i & 511;
    int row = (i >> 9) % KVIN;
    int r = i / (512 * KVIN);
    float v = (col < HH) ? Wk[((size_t)r * KVIN + row) * HH + col]
                         : Wv[((size_t)r * KVIN + row) * HH + col - HH];
    split2(v, g_Wkv_h[i], g_Wkv_l[i]);
}

__global__ void pack_bkv_kernel(const float* __restrict__ bk,
                                const float* __restrict__ bv)
{
    int i = blockIdx.x * 256 + threadIdx.x;
    if (i >= RR * 512) return;
    int col = i & 511;
    int r = i >> 9;
    g_bkv[i] = (col < HH) ? bk[r * HH + col] : bv[r * HH + col - HH];
}

// ---------------- per-relation kernels ----------------
// zero agg + denom (once, before loop)
__global__ void init0_kernel()
{
    int n = blockIdx.x, t = threadIdx.x;
    g_agg[(size_t)n * HH + t] = 0.0f;
    if (t < NHH) g_denom[n * NHH + t] = 0.0f;
}

// fused attention: score -> exp -> accumulate denom AND unnormalized ex*v.
__global__ void attn_kernel(const int* __restrict__ dst_r,
                            const float* __restrict__ prior_r)
{
    int e = blockIdx.x, t = threadIdx.x;
    int h = t >> 5, lane = t & 31;
    float p = g_qb[e * HH + t] * g_kvb[e * 512 + t];
#pragma unroll
    for (int o = 16; o > 0; o >>= 1) p += __shfl_down_sync(0xFFFFFFFFu, p, o);
    float ex;
    if (lane == 0) ex = expf(p * 0.17677669529663689f * prior_r[h]);
    ex = __shfl_sync(0xFFFFFFFFu, ex, 0);
    int dst = dst_r[e];
    if (lane == 0) atomicAdd(&g_denom[dst * NHH + h], ex);
    atomicAdd(&g_agg[(size_t)dst * HH + t], ex * g_kvb[e * 512 + 256 + t]);
}

// normalize agg by denom, split to bf16 planes, re-zero agg/denom
__global__ void split_reset_kernel()
{
    int n = blockIdx.x, t = threadIdx.x;
    size_t idx = (size_t)n * HH + t;
    float den = g_denom[n * NHH + (t >> 5)] + 1e-16f;
    float v = g_agg[idx] / den;
    split2(v, g_agg_h[idx], g_agg_l[idx]);
    g_agg[idx] = 0.0f;
    __syncthreads();
    if (t < NHH) g_denom[n * NHH + t] = 0.0f;
}

// ---------------- inter-relation fusion (reads bf16 relout planes) --------
__global__ void inter_kernel(const float* __restrict__ Wir2,
                             const float* __restrict__ bir2)
{
    int n = blockIdx.x, t = threadIdx.x;
    int w = t >> 5, lane = t & 31;
    __shared__ float logit[RR];
    if (w < RR) {
        float s = 0.0f;
        for (int i = lane; i < HH; i += 32)
            s += g_h[(size_t)n * HH + i] * Wir2[i * RR + w];
#pragma unroll
        for (int o = 16; o > 0; o >>= 1) s += __shfl_down_sync(0xFFFFFFFFu, s, o);
        if (lane == 0) logit[w] = s + bir2[w];
    }
    __syncthreads();
    float l[RR]; float mx = -1e30f;
#pragma unroll
    for (int r = 0; r < RR; r++) { l[r] = logit[r]; mx = fmaxf(mx, l[r]); }
    float sum = 0.0f;
#pragma unroll
    for (int r = 0; r < RR; r++) { l[r] = expf(l[r] - mx); sum += l[r]; }
    float inv = 1.0f / sum;
    int c = t;
    const bf16* roh = g_relout_h + (size_t)n * (RR * HH);
    const bf16* rol = g_relout_l + (size_t)n * (RR * HH);
    float rv[RR];
    float acc = 0.0f;
#pragma unroll
    for (int r = 0; r < RR; r++) {
        rv[r] = b2f(roh[r * HH + c]) + b2f(rol[r * HH + c]);
        acc += l[r] * inv * rv[r];
    }
    g_interagg[(size_t)n * HH + c] = acc;
    size_t base = (size_t)n * 3 * HH;
    split2(rv[2] + rv[3], g_paths_h[base + c],          g_paths_l[base + c]);
    split2(rv[4] + rv[0], g_paths_h[base + HH + c],     g_paths_l[base + HH + c]);
    split2(rv[1] + rv[5], g_paths_h[base + 2 * HH + c], g_paths_l[base + 2 * HH + c]);
}

__global__ void meta_kernel(const float* __restrict__ Wa2,
                            const float* __restrict__ gm,
                            const float* __restrict__ bm_)
{
    int n = blockIdx.x, t = threadIdx.x;
    int w = t >> 5, lane = t & 31;
    __shared__ float sl[3];
    __shared__ float red[HH];
    __shared__ float s_mu, s_var;
    if (w < 3) {
        float s = 0.0f;
        for (int i = lane; i < HH / 2; i += 32)
            s += g_t[((size_t)n * 3 + w) * (HH / 2) + i] * Wa2[i];
#pragma unroll
        for (int o = 16; o > 0; o >>= 1) s += __shfl_down_sync(0xFFFFFFFFu, s, o);
        if (lane == 0) sl[w] = s;
    }
    __syncthreads();
    float a0 = sl[0], a1 = sl[1], a2 = sl[2];
    float mx = fmaxf(a0, fmaxf(a1, a2));
    float e0 = expf(a0 - mx), e1 = expf(a1 - mx), e2 = expf(a2 - mx);
    float inv = 1.0f / (e0 + e1 + e2);
    int c = t;
    const bf16* sth = g_stacked_h + (size_t)n * 3 * HH;
    const bf16* stl = g_stacked_l + (size_t)n * 3 * HH;
    float s0 = b2f(sth[c])          + b2f(stl[c]);
    float s1 = b2f(sth[HH + c])     + b2f(stl[HH + c]);
    float s2 = b2f(sth[2 * HH + c]) + b2f(stl[2 * HH + c]);
    float mpre = (e0 * s0 + e1 * s1 + e2 * s2) * inv;
    red[t] = mpre; __syncthreads();
    for (int s = 128; s > 0; s >>= 1) { if (t < s) red[t] += red[t + s]; __syncthreads(); }
    if (t == 0) s_mu = red[0] * (1.0f / HH);
    __syncthreads();
    float d = mpre - s_mu;
    red[t] = d * d; __syncthreads();
    for (int s = 128; s > 0; s >>= 1) { if (t < s) red[t] += red[t + s]; __syncthreads(); }
    if (t == 0) s_var = red[0] * (1.0f / HH);
    __syncthreads();
    float meta = d * rsqrtf(s_var + 1e-5f) * gm[c] + bm_[c];
    size_t base = (size_t)n * 2 * HH;
    split2(g_interagg[(size_t)n * HH + c], g_combin_h[base + c],      g_combin_l[base + c]);
    split2(meta,                           g_combin_h[base + HH + c], g_combin_l[base + HH + c]);
}

__global__ void final_kernel(const float* __restrict__ x,
                             const float* __restrict__ g,
                             const float* __restrict__ b,
                             float* __restrict__ out)
{
    int n = blockIdx.x, t = threadIdx.x;
    __shared__ float red[HH];
    __shared__ float s_mu, s_var;
    float v = x[(size_t)n * HH + t] + g_comb[(size_t)n * HH + t];
    red[t] = v; __syncthreads();
    for (int s = 128; s > 0; s >>= 1) { if (t < s) red[t] += red[t + s]; __syncthreads(); }
    if (t == 0) s_mu = red[0] * (1.0f / HH);
    __syncthreads();
    float d = v - s_mu;
    red[t] = d * d; __syncthreads();
    for (int s = 128; s > 0; s >>= 1) { if (t < s) red[t] += red[t + s]; __syncthreads(); }
    if (t == 0) s_var = red[0] * (1.0f / HH);
    __syncthreads();
    out[(size_t)n * HH + t] = d * rsqrtf(s_var + 1e-5f) * g[t] + b[t];
}

// ---------------- host ----------------
static inline void run_gemm(const bf16* Ah, const bf16* Al, int lda, long long sA,
                            const int* ridx, const bf16* A2h, const bf16* A2l,
                            const bf16* Bh, const bf16* Bl, int ldb, long long sB,
                            const float* bias, int sBias,
                            float* C, int ldc, long long sC,
                            bf16* Ch, bf16* Cl, int ldc2, long long sC2,
                            int M, int Nc, int K, int act, int Z)
{
    dim3 grid(Nc / 128, (M + 127) / 128, Z);
    mma_gemm<<<grid, 256, GEMM_SMEM>>>(Ah, Al, lda, sA, ridx, A2h, A2l,
                                       Bh, Bl, ldb, sB, bias, sBias,
                                       C, ldc, sC, Ch, Cl, ldc2, sC2,
                                       M, Nc, K, act);
}
static inline void run_split(const float* src, bf16* hi, bf16* lo, size_t n)
{
    split_kernel<<<(unsigned)((n + 255) / 256), 256>>>(src, hi, lo, (int)n);
}

extern "C" void kernel_launch(void* const* d_in, const int* in_sizes, int n_in,
                              void* d_out, int out_size)
{
    const float* x    = (const float*)d_in[0];
    const int*   ei   = (const int*)d_in[1];
    const float* ea   = (const float*)d_in[2];
    const float* Wq   = (const float*)d_in[3];
    const float* bq   = (const float*)d_in[4];
    const float* Wk   = (const float*)d_in[5];
    const float* bk   = (const float*)d_in[6];
    const float* Wv   = (const float*)d_in[7];
    const float* bv   = (const float*)d_in[8];
    const float* prior= (const float*)d_in[9];
    const float* Wm   = (const float*)d_in[10];
    const float* bm   = (const float*)d_in[11];
    const float* Wir1 = (const float*)d_in[12];
    const float* bir1 = (const float*)d_in[13];
    const float* Wir2 = (const float*)d_in[14];
    const float* bir2 = (const float*)d_in[15];
    const float* Wmp  = (const float*)d_in[16];
    const float* bmp  = (const float*)d_in[17];
    const float* Wa1  = (const float*)d_in[18];
    const float* ba1  = (const float*)d_in[19];
    const float* Wa2  = (const float*)d_in[20];
    const float* gme  = (const float*)d_in[21];
    const float* bme  = (const float*)d_in[22];
    const float* Wc   = (const float*)d_in[23];
    const float* bc   = (const float*)d_in[24];
    const float* gout = (const float*)d_in[25];
    const float* bout = (const float*)d_in[26];
    float* out = (float*)d_out;

    cudaFuncSetAttribute(mma_gemm,
                         cudaFuncAttributeMaxDynamicSharedMemorySize, GEMM_SMEM);

#define SYM(p, s) { void* tmp; cudaGetSymbolAddress(&tmp, s); p = (decltype(p))tmp; }
    float *p_kvb, *p_qb, *p_h, *p_t, *p_comb, *p_bkv;
    SYM(p_kvb, g_kvb); SYM(p_qb, g_qb);
    SYM(p_h, g_h); SYM(p_t, g_t); SYM(p_comb, g_comb); SYM(p_bkv, g_bkv);
    bf16 *x_h, *x_l, *ea_h, *ea_l, *agg_h, *agg_l,
         *relout_h, *relout_l, *paths_h, *paths_l, *stacked_h, *stacked_l,
         *combin_h, *combin_l;
    SYM(x_h, g_x_h);   SYM(x_l, g_x_l);
    SYM(ea_h, g_ea_h); SYM(ea_l, g_ea_l);
    SYM(agg_h, g_agg_h);   SYM(agg_l, g_agg_l);
    SYM(relout_h, g_relout_h); SYM(relout_l, g_relout_l);
    SYM(paths_h, g_paths_h);   SYM(paths_l, g_paths_l);
    SYM(stacked_h, g_stacked_h); SYM(stacked_l, g_stacked_l);
    SYM(combin_h, g_combin_h);   SYM(combin_l, g_combin_l);
    bf16 *Wq_h, *Wq_l, *Wkv_h, *Wkv_l, *Wm_h, *Wm_l,
         *Wir1_h, *Wir1_l, *Wmp_h, *Wmp_l, *Wa1_h, *Wa1_l, *Wc_h, *Wc_l;
    SYM(Wq_h, g_Wq_h); SYM(Wq_l, g_Wq_l);
    SYM(Wkv_h, g_Wkv_h); SYM(Wkv_l, g_Wkv_l);
    SYM(Wm_h, g_Wm_h); SYM(Wm_l, g_Wm_l);
    SYM(Wir1_h, g_Wir1_h); SYM(Wir1_l, g_Wir1_l);
    SYM(Wmp_h, g_Wmp_h);   SYM(Wmp_l, g_Wmp_l);
    SYM(Wa1_h, g_Wa1_h);   SYM(Wa1_l, g_Wa1_l);
    SYM(Wc_h, g_Wc_h);     SYM(Wc_l, g_Wc_l);
#undef SYM

    // one-time splits: x, edge_attr, weights
    run_split(x,    x_h,    x_l,    NN * HH);
    run_split(ea,   ea_h,   ea_l,   RR * EE * FF);
    run_split(Wq,   Wq_h,   Wq_l,   RR * HH * HH);
    pack_kv_kernel<<<(RR * KVIN * 512 + 255) / 256, 256>>>(Wk, Wv);
    pack_bkv_kernel<<<(RR * 512 + 255) / 256, 256>>>(bk, bv);
    run_split(Wm,   Wm_h,   Wm_l,   RR * HH * HH);
    run_split(Wir1, Wir1_h, Wir1_l, RR * HH * HH);
    run_split(Wmp,  Wmp_h,  Wmp_l,  3 * HH * HH);
    run_split(Wa1,  Wa1_h,  Wa1_l,  HH * HH / 2);
    run_split(Wc,   Wc_h,   Wc_l,   2 * HH * HH);

    init0_kernel<<<NN, 256>>>();

    // per-relation pipeline (gather fused into GEMM A-path)
    for (int r = 0; r < RR; r++) {
        const int* ei_r  = ei + (size_t)r * 2 * EE;
        const int* src_r = ei_r;
        const int* dst_r = ei_r + EE;
        const bf16* ea_h_r = ea_h + (size_t)r * EE * FF;
        const bf16* ea_l_r = ea_l + (size_t)r * EE * FF;

        // kv = [x[src] | ea] @ [Wk|Wv] + [bk|bv]   (fused, Nc=512)
        run_gemm(x_h, x_l, HH, 0, src_r, ea_h_r, ea_l_r,
                 Wkv_h + (size_t)r * KVIN * 512, Wkv_l + (size_t)r * KVIN * 512,
                 512, 0, p_bkv + r * 512, 0,
                 p_kvb, 512, 0, nullptr, nullptr, 0, 0,
                 EE, 512, KVIN, 0, 1);
        // q = x[dst] @ Wq + bq
        run_gemm(x_h, x_l, HH, 0, dst_r, nullptr, nullptr,
                 Wq_h + (size_t)r * HH * HH, Wq_l + (size_t)r * HH * HH,
                 HH, 0, bq + r * HH, 0,
                 p_qb, HH, 0, nullptr, nullptr, 0, 0,
                 EE, HH, HH, 0, 1);
        // fused attention: exp(score) -> denom + unnormalized ex*v
        attn_kernel<<<EE, 256>>>(dst_r, prior + r * NHH);
        // normalize + split agg, reset agg/denom
        split_reset_kernel<<<NN, 256>>>();
        // rel_out[r] = gelu(agg @ Wm + bm) -> bf16 planes only, col slice r*H
        run_gemm(agg_h, agg_l, HH, 0, nullptr, nullptr, nullptr,
                 Wm_h + (size_t)r * HH * HH, Wm_l + (size_t)r * HH * HH,
                 HH, 0, bm + r * HH, 0,
                 nullptr, 0, 0,
                 relout_h + r * HH, relout_l + r * HH, RR * HH, 0,
                 NN, HH, HH, 1, 1);
    }

    // h = gelu(all_rel @ W_ir1 + b_ir1)
    run_gemm(relout_h, relout_l, RR * HH, 0, nullptr, nullptr, nullptr,
             Wir1_h, Wir1_l, HH, 0, bir1, 0,
             p_h, HH, 0, nullptr, nullptr, 0, 0,
             NN, HH, RR * HH, 1, 1);
    inter_kernel<<<NN, 256>>>(Wir2, bir2);
    // stacked[p] = paths[p] @ Wmp[p] + bmp[p] -> bf16 planes only
    run_gemm(paths_h, paths_l, 3 * HH, HH, nullptr, nullptr, nullptr,
             Wmp_h, Wmp_l, HH, (long long)HH * HH, bmp, HH,
             nullptr, 0, 0,
             stacked_h, stacked_l, 3 * HH, HH,
             NN, HH, HH, 0, 3);
    // t = tanh(stacked @ Wa1 + ba1)
    run_gemm(stacked_h, stacked_l, HH, 0, nullptr, nullptr, nullptr,
             Wa1_h, Wa1_l, HH / 2, 0, ba1, 0,
             p_t, HH / 2, 0, nullptr, nullptr, 0, 0,
             3 * NN, HH / 2, HH, 2, 1);
    meta_kernel<<<NN, 256>>>(Wa2, gme, bme);
    // combined = gelu([inter_agg, meta] @ Wc + bc)
    run_gemm(combin_h, combin_l, 2 * HH, 0, nullptr, nullptr, nullptr,
             Wc_h, Wc_l, HH, 0, bc, 0,
             p_comb, HH, 0, nullptr, nullptr, 0, 0,
             NN, HH, 2 * HH, 1, 1);
    final_kernel<<<NN, 256>>>(x, gout, bout, out);
}